// round 3
// baseline (speedup 1.0000x reference)
#include <cuda_runtime.h>
#include <math.h>

#define Bb 4
#define Tt 2048
#define Dd 256
#define BT (Bb*Tt)
#define BTD (Bb*Tt*Dd)

// Scratch (static __device__ — no allocations allowed)
__device__ float g_q[BTD];
__device__ float g_k[BTD];   // scaled by 1/sqrt(D)
__device__ float g_v[BTD];
__device__ float g_li[BTD];  // log_i, overwritten in place with i_s by chan_scan
__device__ float g_lf[BTD];  // log_f, overwritten in place with f_s by chan_scan
__device__ float g_o[BTD];   // o_pre
__device__ float g_n[BTD];
__device__ float g_den[BT];

// ---------------------------------------------------------------------------
// Kernel 1: fused projection GEMM  (8192 x 1536 x 256, fp32)
// N segments: [0,256)=q  [256,512)=k  [512,768)=v  [768,1536)=gates(Wg)
// ---------------------------------------------------------------------------
__global__ __launch_bounds__(256) void proj_gemm(
    const float* __restrict__ x,
    const float* __restrict__ Wq, const float* __restrict__ bq,
    const float* __restrict__ Wk, const float* __restrict__ bk,
    const float* __restrict__ Wv, const float* __restrict__ bv,
    const float* __restrict__ Wg, const float* __restrict__ bg,
    const float* __restrict__ ib)
{
    __shared__ float As[64][20];   // [m][k] padded
    __shared__ float Bs[16][64];   // [k][n]

    const int tid   = threadIdx.x;
    const int mBase = blockIdx.y * 64;
    const int nBase = blockIdx.x * 64;

    const float* W;  const float* bias;  float* outArr;
    int ldw, colW, outCol, mode;
    if (nBase < 256)      { W = Wq; ldw = 256; colW = nBase;       bias = bq; outArr = g_q;  mode = 0; }
    else if (nBase < 512) { W = Wk; ldw = 256; colW = nBase - 256; bias = bk; outArr = g_k;  mode = 1; }
    else if (nBase < 768) { W = Wv; ldw = 256; colW = nBase - 512; bias = bv; outArr = g_v;  mode = 0; }
    else {
        W = Wg; ldw = 768; colW = nBase - 768; bias = bg;
        int gi = colW >> 8;
        outArr = (gi == 0) ? g_li : ((gi == 1) ? g_lf : g_o);
        mode   = (gi == 0) ? 2 : ((gi == 1) ? 3 : 0);
    }
    outCol = (nBase < 768) ? colW : (colW & 255);

    const int aRow = tid >> 2, aK = (tid & 3) << 2;
    const int bK   = tid >> 4, bN = (tid & 15) << 2;
    const int tx   = tid & 15, ty = tid >> 4;

    float acc[4][4] = {};

    for (int k0 = 0; k0 < 256; k0 += 16) {
        float4 av  = *(const float4*)(x + (size_t)(mBase + aRow) * 256 + k0 + aK);
        float4 bv4 = *(const float4*)(W + (size_t)(k0 + bK) * ldw + colW + bN);
        __syncthreads();
        *(float4*)&As[aRow][aK] = av;
        *(float4*)&Bs[bK][bN]   = bv4;
        __syncthreads();
        #pragma unroll
        for (int kk = 0; kk < 16; kk++) {
            float a0 = As[ty*4+0][kk];
            float a1 = As[ty*4+1][kk];
            float a2 = As[ty*4+2][kk];
            float a3 = As[ty*4+3][kk];
            float4 bb = *(const float4*)&Bs[kk][tx*4];
            acc[0][0] = fmaf(a0, bb.x, acc[0][0]); acc[0][1] = fmaf(a0, bb.y, acc[0][1]);
            acc[0][2] = fmaf(a0, bb.z, acc[0][2]); acc[0][3] = fmaf(a0, bb.w, acc[0][3]);
            acc[1][0] = fmaf(a1, bb.x, acc[1][0]); acc[1][1] = fmaf(a1, bb.y, acc[1][1]);
            acc[1][2] = fmaf(a1, bb.z, acc[1][2]); acc[1][3] = fmaf(a1, bb.w, acc[1][3]);
            acc[2][0] = fmaf(a2, bb.x, acc[2][0]); acc[2][1] = fmaf(a2, bb.y, acc[2][1]);
            acc[2][2] = fmaf(a2, bb.z, acc[2][2]); acc[2][3] = fmaf(a2, bb.w, acc[2][3]);
            acc[3][0] = fmaf(a3, bb.x, acc[3][0]); acc[3][1] = fmaf(a3, bb.y, acc[3][1]);
            acc[3][2] = fmaf(a3, bb.z, acc[3][2]); acc[3][3] = fmaf(a3, bb.w, acc[3][3]);
        }
    }

    #pragma unroll
    for (int i = 0; i < 4; i++) {
        int row = mBase + ty*4 + i;
        #pragma unroll
        for (int j = 0; j < 4; j++) {
            int nl = tx*4 + j;
            float val = acc[i][j] + bias[colW + nl];
            if (mode == 1) {
                val *= 0.0625f;                              // 1/sqrt(256)
            } else if (mode == 2) {
                val += ib[outCol + nl];
                val = 10.0f * tanhf(val * 0.1f);             // softcap
            } else if (mode == 3) {
                val = -(fmaxf(val, 0.0f) + log1pf(__expf(-fabsf(val))));  // -softplus
            }
            outArr[(size_t)row * 256 + outCol + nl] = val;
        }
    }
}

// ---------------------------------------------------------------------------
// Kernel 2: per-channel scan  (m, i_s, f_s, n)   one thread per (b,d)
// ---------------------------------------------------------------------------
__device__ __forceinline__ void cs_load(size_t base, int g,
    float (&li)[8], float (&lf)[8], float (&kk)[8])
{
    #pragma unroll
    for (int u = 0; u < 8; u++) {
        size_t idx = base + (size_t)(g*8 + u) * Dd;
        li[u] = g_li[idx]; lf[u] = g_lf[idx]; kk[u] = g_k[idx];
    }
}
__device__ __forceinline__ void cs_proc(size_t base, int g,
    const float (&li)[8], const float (&lf)[8], const float (&kk)[8],
    float& m, float& n)
{
    #pragma unroll
    for (int u = 0; u < 8; u++) {
        size_t idx = base + (size_t)(g*8 + u) * Dd;
        float mn = fmaxf(lf[u] + m, li[u]);
        float is = __expf(li[u] - mn);
        float fs = __expf(lf[u] + m - mn);
        n = fmaf(fs, n, is * kk[u]);
        g_li[idx] = is;
        g_lf[idx] = fs;
        g_n[idx]  = n;
        m = mn;
    }
}
__global__ __launch_bounds__(32) void chan_scan()
{
    const int b = blockIdx.x >> 3;
    const int d = ((blockIdx.x & 7) << 5) + threadIdx.x;
    size_t base = (size_t)b * Tt * Dd + d;
    float m = 0.0f, n = 0.0f;
    float liA[8], lfA[8], kA[8], liB[8], lfB[8], kB[8];
    const int NG = Tt / 8;   // 256
    cs_load(base, 0, liA, lfA, kA);
    for (int g = 0; g < NG; g += 2) {
        cs_load(base, g + 1, liB, lfB, kB);
        cs_proc(base, g, liA, lfA, kA, m, n);
        if (g + 2 < NG) cs_load(base, g + 2, liA, lfA, kA);
        cs_proc(base, g + 1, liB, lfB, kB, m, n);
    }
}

// ---------------------------------------------------------------------------
// Kernel 3: denom[b,t] = max(|n_t . q_t|, 1e-6)    one warp per (b,t)
// ---------------------------------------------------------------------------
__global__ __launch_bounds__(256) void denom_kernel()
{
    const int gw   = blockIdx.x * 8 + (threadIdx.x >> 5);
    const int lane = threadIdx.x & 31;
    size_t base = (size_t)gw * Dd + lane * 8;
    float4 n1 = *(const float4*)&g_n[base];
    float4 n2 = *(const float4*)&g_n[base + 4];
    float4 q1 = *(const float4*)&g_q[base];
    float4 q2 = *(const float4*)&g_q[base + 4];
    float s = n1.x*q1.x + n1.y*q1.y + n1.z*q1.z + n1.w*q1.w
            + n2.x*q2.x + n2.y*q2.y + n2.z*q2.z + n2.w*q2.w;
    #pragma unroll
    for (int o = 16; o; o >>= 1) s += __shfl_xor_sync(0xffffffffu, s, o);
    if (lane == 0) g_den[gw] = fmaxf(fabsf(s), 1e-6f);
}

// ---------------------------------------------------------------------------
// Kernel 4: main sequential scan.  CTA = 8 warps = 8 M-rows of one batch.
// Warp w owns M[row,:] in registers (8 floats/lane). cp.async 4-stage pipeline.
// ---------------------------------------------------------------------------
#define STAGES 4
__device__ __forceinline__ void cpa16(void* sm, const void* g) {
    unsigned s = (unsigned)__cvta_generic_to_shared(sm);
    asm volatile("cp.async.ca.shared.global [%0], [%1], 16;" :: "r"(s), "l"(g));
}
__device__ __forceinline__ void cpa4(void* sm, const void* g) {
    unsigned s = (unsigned)__cvta_generic_to_shared(sm);
    asm volatile("cp.async.ca.shared.global [%0], [%1], 4;" :: "r"(s), "l"(g));
}

__global__ __launch_bounds__(256) void main_scan(float* __restrict__ out)
{
    __shared__ __align__(16) float s_kq[STAGES][512];  // k[256] | q[256]
    __shared__ __align__(16) float s_sc[STAGES][32];   // v[8] is[8] fs[8] op[8]
    __shared__ __align__(16) float s_den[STAGES][4];

    const int tid     = threadIdx.x;
    const int w       = tid >> 5;
    const int lane    = tid & 31;
    const int b       = blockIdx.x >> 5;
    const int rowBase = (blockIdx.x & 31) << 3;
    const size_t bBase = (size_t)b * Tt * Dd;

    auto issue = [&](int st, int t) {
        size_t base = bBase + (size_t)t * Dd;
        if (tid < 64) {
            cpa16(&s_kq[st][tid * 4], g_k + base + tid * 4);
        } else if (tid < 128) {
            cpa16(&s_kq[st][256 + (tid - 64) * 4], g_q + base + (tid - 64) * 4);
        } else if (tid < 136) {
            int a = (tid - 128) >> 1, p = (tid - 128) & 1;
            const float* sp = (a == 0) ? g_v : (a == 1) ? g_li : (a == 2) ? g_lf : g_o;
            cpa16(&s_sc[st][a * 8 + p * 4], sp + base + rowBase + p * 4);
        } else if (tid == 136) {
            cpa4(&s_den[st][0], &g_den[(size_t)b * Tt + t]);
        }
    };

    float Mr[8];
    #pragma unroll
    for (int i = 0; i < 8; i++) Mr[i] = 0.0f;

    #pragma unroll
    for (int s = 0; s < STAGES - 1; ++s) {
        issue(s, s);
        asm volatile("cp.async.commit_group;");
    }

    for (int t = 0; t < Tt; ++t) {
        asm volatile("cp.async.wait_group %0;" :: "n"(STAGES - 2));
        __syncthreads();
        int tp = t + STAGES - 1;
        if (tp < Tt) issue(tp & (STAGES - 1), tp);
        asm volatile("cp.async.commit_group;");

        const int st = t & (STAGES - 1);
        const float4 ka = *(const float4*)&s_kq[st][lane * 8];
        const float4 kb = *(const float4*)&s_kq[st][lane * 8 + 4];
        const float4 qa = *(const float4*)&s_kq[st][256 + lane * 8];
        const float4 qb = *(const float4*)&s_kq[st][256 + lane * 8 + 4];
        const float vv  = s_sc[st][w];
        const float is  = s_sc[st][8 + w];
        const float fs  = s_sc[st][16 + w];
        const float op  = s_sc[st][24 + w];
        const float den = s_den[st][0];
        const float iv  = is * vv;

        Mr[0] = fmaf(fs, Mr[0], iv * ka.x);
        Mr[1] = fmaf(fs, Mr[1], iv * ka.y);
        Mr[2] = fmaf(fs, Mr[2], iv * ka.z);
        Mr[3] = fmaf(fs, Mr[3], iv * ka.w);
        Mr[4] = fmaf(fs, Mr[4], iv * kb.x);
        Mr[5] = fmaf(fs, Mr[5], iv * kb.y);
        Mr[6] = fmaf(fs, Mr[6], iv * kb.z);
        Mr[7] = fmaf(fs, Mr[7], iv * kb.w);

        float a0 = Mr[0] * qa.x;
        float a1 = Mr[1] * qa.y;
        a0 = fmaf(Mr[2], qa.z, a0);
        a1 = fmaf(Mr[3], qa.w, a1);
        a0 = fmaf(Mr[4], qb.x, a0);
        a1 = fmaf(Mr[5], qb.y, a1);
        a0 = fmaf(Mr[6], qb.z, a0);
        a1 = fmaf(Mr[7], qb.w, a1);
        float acc = a0 + a1;

        #pragma unroll
        for (int o = 16; o; o >>= 1) acc += __shfl_xor_sync(0xffffffffu, acc, o);

        if (lane == 0) {
            float sig = 1.0f / (1.0f + __expf(-op));
            out[bBase + (size_t)t * Dd + rowBase + w] = sig * acc / den;
        }
    }
}

// ---------------------------------------------------------------------------
// Kernel 5: RMSNorm in place on d_out.  One warp per (b,t) row.
// ---------------------------------------------------------------------------
__global__ __launch_bounds__(256) void rmsnorm_kernel(float* __restrict__ out,
                                                      const float* __restrict__ ns)
{
    const int gw   = blockIdx.x * 8 + (threadIdx.x >> 5);
    const int lane = threadIdx.x & 31;
    size_t base = (size_t)gw * Dd + lane * 8;
    float4 a = *(const float4*)&out[base];
    float4 c = *(const float4*)&out[base + 4];
    float ss = a.x*a.x + a.y*a.y + a.z*a.z + a.w*a.w
             + c.x*c.x + c.y*c.y + c.z*c.z + c.w*c.w;
    #pragma unroll
    for (int o = 16; o; o >>= 1) ss += __shfl_xor_sync(0xffffffffu, ss, o);
    float rinv = rsqrtf(ss * (1.0f / Dd) + 1e-8f);
    float4 s1 = *(const float4*)&ns[lane * 8];
    float4 s2 = *(const float4*)&ns[lane * 8 + 4];
    a.x *= rinv * s1.x; a.y *= rinv * s1.y; a.z *= rinv * s1.z; a.w *= rinv * s1.w;
    c.x *= rinv * s2.x; c.y *= rinv * s2.y; c.z *= rinv * s2.z; c.w *= rinv * s2.w;
    *(float4*)&out[base]     = a;
    *(float4*)&out[base + 4] = c;
}

// ---------------------------------------------------------------------------
extern "C" void kernel_launch(void* const* d_in, const int* in_sizes, int n_in,
                              void* d_out, int out_size)
{
    const float* x  = (const float*)d_in[0];
    const float* Wq = (const float*)d_in[1];
    const float* bq = (const float*)d_in[2];
    const float* Wk = (const float*)d_in[3];
    const float* bk = (const float*)d_in[4];
    const float* Wv = (const float*)d_in[5];
    const float* bv = (const float*)d_in[6];
    const float* Wg = (const float*)d_in[7];
    const float* bg = (const float*)d_in[8];
    const float* ib = (const float*)d_in[9];
    const float* ns = (const float*)d_in[10];
    float* out = (float*)d_out;

    dim3 ggrid(24, 128);   // N tiles x M tiles
    proj_gemm<<<ggrid, 256>>>(x, Wq, bq, Wk, bk, Wv, bv, Wg, bg, ib);
    chan_scan<<<32, 32>>>();
    denom_kernel<<<1024, 256>>>();
    main_scan<<<128, 256>>>(out);
    rmsnorm_kernel<<<1024, 256>>>(out, ns);
}

// round 4
// speedup vs baseline: 2.4052x; 2.4052x over previous
#include <cuda_runtime.h>
#include <math.h>

#define Bb 4
#define Tt 2048
#define Dd 256
#define BT (Bb*Tt)
#define BTD (Bb*Tt*Dd)
#define CC 64
#define NC 32
#define NCH 33

// Scratch (static __device__ — no allocations allowed)
__device__ float g_q[BTD];
__device__ float g_k[BTD];            // scaled by 1/sqrt(D)
__device__ float g_v[BTD];            // -> U after prep
__device__ float g_li[BTD];           // log_i -> E=li-b (chan) -> Gamma (prep)
__device__ float g_lf[BTD];           // log_f -> b-m (chan)   -> G     (prep)
__device__ float g_o[BTD];            // o_pre -> sigmoid(o) (prep)
__device__ float g_n[BTD];
__device__ float g_den[BT];
__device__ float g_S[Bb*NC*CC*CC];    // masked scores S[s][t]
__device__ float g_m[Bb*NCH*Dd];      // m at chunk starts + final
__device__ float g_bend[Bb*NC*Dd];

// ---------------------------------------------------------------------------
// Kernel 1: fused projection GEMM  (8192 x 1536 x 256, fp32)
// ---------------------------------------------------------------------------
__global__ __launch_bounds__(256) void proj_gemm(
    const float* __restrict__ x,
    const float* __restrict__ Wq, const float* __restrict__ bq,
    const float* __restrict__ Wk, const float* __restrict__ bk,
    const float* __restrict__ Wv, const float* __restrict__ bv,
    const float* __restrict__ Wg, const float* __restrict__ bg,
    const float* __restrict__ ib)
{
    __shared__ float As[64][20];
    __shared__ float Bs[16][64];

    const int tid   = threadIdx.x;
    const int mBase = blockIdx.y * 64;
    const int nBase = blockIdx.x * 64;

    const float* W;  const float* bias;  float* outArr;
    int ldw, colW, outCol, mode;
    if (nBase < 256)      { W = Wq; ldw = 256; colW = nBase;       bias = bq; outArr = g_q;  mode = 0; }
    else if (nBase < 512) { W = Wk; ldw = 256; colW = nBase - 256; bias = bk; outArr = g_k;  mode = 1; }
    else if (nBase < 768) { W = Wv; ldw = 256; colW = nBase - 512; bias = bv; outArr = g_v;  mode = 0; }
    else {
        W = Wg; ldw = 768; colW = nBase - 768; bias = bg;
        int gi = colW >> 8;
        outArr = (gi == 0) ? g_li : ((gi == 1) ? g_lf : g_o);
        mode   = (gi == 0) ? 2 : ((gi == 1) ? 3 : 0);
    }
    outCol = (nBase < 768) ? colW : (colW & 255);

    const int aRow = tid >> 2, aK = (tid & 3) << 2;
    const int bK   = tid >> 4, bN = (tid & 15) << 2;
    const int tx   = tid & 15, ty = tid >> 4;

    float acc[4][4] = {};

    for (int k0 = 0; k0 < 256; k0 += 16) {
        float4 av  = *(const float4*)(x + (size_t)(mBase + aRow) * 256 + k0 + aK);
        float4 bv4 = *(const float4*)(W + (size_t)(k0 + bK) * ldw + colW + bN);
        __syncthreads();
        *(float4*)&As[aRow][aK] = av;
        *(float4*)&Bs[bK][bN]   = bv4;
        __syncthreads();
        #pragma unroll
        for (int kk = 0; kk < 16; kk++) {
            float a0 = As[ty*4+0][kk];
            float a1 = As[ty*4+1][kk];
            float a2 = As[ty*4+2][kk];
            float a3 = As[ty*4+3][kk];
            float4 bb = *(const float4*)&Bs[kk][tx*4];
            acc[0][0] = fmaf(a0, bb.x, acc[0][0]); acc[0][1] = fmaf(a0, bb.y, acc[0][1]);
            acc[0][2] = fmaf(a0, bb.z, acc[0][2]); acc[0][3] = fmaf(a0, bb.w, acc[0][3]);
            acc[1][0] = fmaf(a1, bb.x, acc[1][0]); acc[1][1] = fmaf(a1, bb.y, acc[1][1]);
            acc[1][2] = fmaf(a1, bb.z, acc[1][2]); acc[1][3] = fmaf(a1, bb.w, acc[1][3]);
            acc[2][0] = fmaf(a2, bb.x, acc[2][0]); acc[2][1] = fmaf(a2, bb.y, acc[2][1]);
            acc[2][2] = fmaf(a2, bb.z, acc[2][2]); acc[2][3] = fmaf(a2, bb.w, acc[2][3]);
            acc[3][0] = fmaf(a3, bb.x, acc[3][0]); acc[3][1] = fmaf(a3, bb.y, acc[3][1]);
            acc[3][2] = fmaf(a3, bb.z, acc[3][2]); acc[3][3] = fmaf(a3, bb.w, acc[3][3]);
        }
    }

    #pragma unroll
    for (int i = 0; i < 4; i++) {
        int row = mBase + ty*4 + i;
        #pragma unroll
        for (int j = 0; j < 4; j++) {
            int nl = tx*4 + j;
            float val = acc[i][j] + bias[colW + nl];
            if (mode == 1) {
                val *= 0.0625f;
            } else if (mode == 2) {
                val += ib[outCol + nl];
                val = 10.0f * tanhf(val * 0.1f);
            } else if (mode == 3) {
                val = -(fmaxf(val, 0.0f) + log1pf(__expf(-fabsf(val))));
            }
            outArr[(size_t)row * 256 + outCol + nl] = val;
        }
    }
}

// ---------------------------------------------------------------------------
// Kernel 2: per-channel scan: m, n; writes E=li-b, bm=b-m, bend, m boundaries
// ---------------------------------------------------------------------------
__global__ __launch_bounds__(32) void chan_scan()
{
    const int b = blockIdx.x >> 3;
    const int d = ((blockIdx.x & 7) << 5) + threadIdx.x;
    size_t base = (size_t)b * Tt * Dd + d;
    float m = 0.0f, n = 0.0f;

    for (int c = 0; c < NC; c++) {
        g_m[(size_t)((b*NCH + c) << 8) + d] = m;
        float bl = 0.0f;
        size_t cb = base + (size_t)c * CC * Dd;
        for (int g = 0; g < CC; g += 8) {
            float li[8], lf[8], kk[8];
            #pragma unroll
            for (int u = 0; u < 8; u++) {
                size_t idx = cb + (size_t)(g + u) * Dd;
                li[u] = g_li[idx]; lf[u] = g_lf[idx]; kk[u] = g_k[idx];
            }
            #pragma unroll
            for (int u = 0; u < 8; u++) {
                size_t idx = cb + (size_t)(g + u) * Dd;
                bl += lf[u];
                float mn = fmaxf(lf[u] + m, li[u]);
                float is = __expf(li[u] - mn);
                float fs = __expf(lf[u] + m - mn);
                n = fmaf(fs, n, is * kk[u]);
                g_n[idx]  = n;
                g_li[idx] = li[u] - bl;
                g_lf[idx] = bl - mn;
                m = mn;
            }
        }
        g_bend[(size_t)((b*NC + c) << 8) + d] = bl;
    }
    g_m[(size_t)((b*NCH + NC) << 8) + d] = m;
}

// ---------------------------------------------------------------------------
// Kernel 3: elementwise prep: U, G, Gamma, sigmoid(o)
// ---------------------------------------------------------------------------
__global__ __launch_bounds__(256) void prep_kernel()
{
    int i4 = blockIdx.x * 256 + threadIdx.x;   // BTD/4 float4 slots
    int d4 = i4 & 63;
    int t  = (i4 >> 6) & 2047;
    int b  = i4 >> 17;
    int c  = t >> 6;

    float4 E  = ((const float4*)g_li)[i4];
    float4 bm = ((const float4*)g_lf)[i4];
    float4 v  = ((const float4*)g_v)[i4];
    float4 op = ((const float4*)g_o)[i4];
    float4 be = ((const float4*)g_bend)[(size_t)(b*NC + c)*64 + d4];
    float4 mp = ((const float4*)g_m)[(size_t)(b*NCH + c)*64 + d4];

    float4 U, G, Ga, sg;
    U.x = __expf(E.x + be.x) * v.x;  U.y = __expf(E.y + be.y) * v.y;
    U.z = __expf(E.z + be.z) * v.z;  U.w = __expf(E.w + be.w) * v.w;
    G.x = __expf(bm.x - be.x); G.y = __expf(bm.y - be.y);
    G.z = __expf(bm.z - be.z); G.w = __expf(bm.w - be.w);
    Ga.x = __expf(bm.x + mp.x); Ga.y = __expf(bm.y + mp.y);
    Ga.z = __expf(bm.z + mp.z); Ga.w = __expf(bm.w + mp.w);
    sg.x = 1.0f/(1.0f + __expf(-op.x)); sg.y = 1.0f/(1.0f + __expf(-op.y));
    sg.z = 1.0f/(1.0f + __expf(-op.z)); sg.w = 1.0f/(1.0f + __expf(-op.w));

    ((float4*)g_v)[i4]  = U;
    ((float4*)g_lf)[i4] = G;
    ((float4*)g_li)[i4] = Ga;
    ((float4*)g_o)[i4]  = sg;
}

// ---------------------------------------------------------------------------
// Kernel 4: denom[b,t] = max(|n_t . q_t|, 1e-6)
// ---------------------------------------------------------------------------
__global__ __launch_bounds__(256) void denom_kernel()
{
    const int gw   = blockIdx.x * 8 + (threadIdx.x >> 5);
    const int lane = threadIdx.x & 31;
    size_t base = (size_t)gw * Dd + lane * 8;
    float4 n1 = *(const float4*)&g_n[base];
    float4 n2 = *(const float4*)&g_n[base + 4];
    float4 q1 = *(const float4*)&g_q[base];
    float4 q2 = *(const float4*)&g_q[base + 4];
    float s = n1.x*q1.x + n1.y*q1.y + n1.z*q1.z + n1.w*q1.w
            + n2.x*q2.x + n2.y*q2.y + n2.z*q2.z + n2.w*q2.w;
    #pragma unroll
    for (int o = 16; o; o >>= 1) s += __shfl_xor_sync(0xffffffffu, s, o);
    if (lane == 0) g_den[gw] = fmaxf(fabsf(s), 1e-6f);
}

// ---------------------------------------------------------------------------
// Kernel 5: per-chunk scores S[s][t] = k_s . q_t  masked (s<=t)
// ---------------------------------------------------------------------------
__global__ __launch_bounds__(256) void score_kernel()
{
    const int b = blockIdx.x >> 5, c = blockIdx.x & 31;
    __shared__ float Qs[64][33];
    __shared__ float Ks[64][33];
    const int tid = threadIdx.x;
    const int sg = tid >> 4, tg = tid & 15;
    float acc[4][4] = {};
    size_t base = ((size_t)b * Tt + c * CC) * Dd;

    for (int db = 0; db < 256; db += 32) {
        __syncthreads();
        for (int l = tid; l < 512; l += 256) {
            int r = l >> 3, q4 = (l & 7) * 4;
            float4 qv = *(const float4*)&g_q[base + (size_t)r*Dd + db + q4];
            float4 kv = *(const float4*)&g_k[base + (size_t)r*Dd + db + q4];
            Qs[r][q4+0]=qv.x; Qs[r][q4+1]=qv.y; Qs[r][q4+2]=qv.z; Qs[r][q4+3]=qv.w;
            Ks[r][q4+0]=kv.x; Ks[r][q4+1]=kv.y; Ks[r][q4+2]=kv.z; Ks[r][q4+3]=kv.w;
        }
        __syncthreads();
        #pragma unroll 8
        for (int dd = 0; dd < 32; dd++) {
            float kv[4], qv[4];
            #pragma unroll
            for (int x = 0; x < 4; x++) { kv[x] = Ks[sg*4+x][dd]; qv[x] = Qs[tg*4+x][dd]; }
            #pragma unroll
            for (int si = 0; si < 4; si++)
                #pragma unroll
                for (int ti = 0; ti < 4; ti++)
                    acc[si][ti] = fmaf(kv[si], qv[ti], acc[si][ti]);
        }
    }

    float* Sp = g_S + (size_t)(b*NC + c) * (CC*CC);
    #pragma unroll
    for (int si = 0; si < 4; si++) {
        int s = sg*4 + si;
        #pragma unroll
        for (int ti = 0; ti < 4; ti++) {
            int t = tg*4 + ti;
            Sp[s*64 + t] = (s <= t) ? acc[si][ti] : 0.0f;
        }
    }
}

// ---------------------------------------------------------------------------
// Kernel 6: chunk scan. CTA = (batch, 8-row block). 32 sequential chunks.
// ---------------------------------------------------------------------------
#define QS_OFF   0            // [64][257]
#define KS_OFF   16448        // [64][257]
#define SS_OFF   32896        // [64][64]
#define MS_OFF   36992        // [256][12] (8 used)
#define US_OFF   40064        // [64][8]  U
#define GS_OFF   40576        // [64][8]  G
#define GAS_OFF  41088        // [64][8]  Gamma
#define OS_OFF   41600        // [64][8]  sigmoid(o)
#define DEN_OFF  42112        // [64] reciprocal den
#define DEC_OFF  42176        // [8]
#define ESC_OFF  42184        // [8]
#define RED_OFF  42192        // [512]
#define SM_FLOATS 42704
#define SM_BYTES  (SM_FLOATS*4)

__global__ __launch_bounds__(256) void chunk_scan(float* __restrict__ out)
{
    extern __shared__ float sm[];
    const int tid = threadIdx.x;
    const int b = blockIdx.x >> 5, rb = blockIdx.x & 31;
    const int rowBase = rb * 8;
    const size_t bB = (size_t)b * Tt * Dd;

    // init M = 0
    {
        int j = tid;
        *(float4*)&sm[MS_OFF + j*12]     = make_float4(0.f,0.f,0.f,0.f);
        *(float4*)&sm[MS_OFF + j*12 + 4] = make_float4(0.f,0.f,0.f,0.f);
    }

    const int t  = tid & 63;
    const int iq = (tid >> 6) & 1;
    const int hf = tid >> 7;

    for (int c = 0; c < NC; c++) {
        const int t0 = c * CC;
        __syncthreads();   // prev chunk's M-update / smem reads done

        // ---- fills ----
        for (int p = tid; p < 8192; p += 256) {
            int arr = p >> 12;
            int idx = p & 4095;
            int r = idx >> 6, c4 = (idx & 63) * 4;
            const float* src = arr ? g_k : g_q;
            float4 v = *(const float4*)&src[bB + (size_t)(t0 + r)*Dd + c4];
            float* dst = &sm[(arr ? KS_OFF : QS_OFF) + r*257 + c4];
            dst[0]=v.x; dst[1]=v.y; dst[2]=v.z; dst[3]=v.w;
        }
        {
            const float4* Sg = (const float4*)(g_S + (size_t)(b*NC + c)*(CC*CC));
            for (int p = tid; p < 1024; p += 256)
                *(float4*)&sm[SS_OFF + p*4] = Sg[p];
        }
        for (int p = tid; p < 512; p += 256) {
            int arr = p >> 7, idx = p & 127;
            int s = idx >> 1, hh = (idx & 1) * 4;
            const float* src = (arr==0) ? g_v : (arr==1) ? g_lf : (arr==2) ? g_li : g_o;
            float4 v = *(const float4*)&src[bB + (size_t)(t0 + s)*Dd + rowBase + hh];
            *(float4*)&sm[US_OFF + arr*512 + s*8 + hh] = v;
        }
        if (tid < 64) sm[DEN_OFF + tid] = 1.0f / g_den[(size_t)b*Tt + t0 + tid];
        if (tid < 8) {
            float be = g_bend[(size_t)(b*NC + c)*Dd + rowBase + tid];
            float mp = g_m[(size_t)(b*NCH + c)*Dd + rowBase + tid];
            float me = g_m[(size_t)(b*NCH + c + 1)*Dd + rowBase + tid];
            sm[DEC_OFF + tid] = __expf(be + mp - me);
            sm[ESC_OFF + tid] = __expf(-me);
        }
        __syncthreads();

        // ---- intra: aA = sum_s S[s][t] * U[s][iq*4..] over s-half ----
        float aA0=0.f, aA1=0.f, aA2=0.f, aA3=0.f;
        #pragma unroll 8
        for (int s = hf*32; s < hf*32 + 32; s++) {
            float f = sm[SS_OFF + s*64 + t];
            float4 u = *(const float4*)&sm[US_OFF + s*8 + iq*4];
            aA0 = fmaf(f, u.x, aA0); aA1 = fmaf(f, u.y, aA1);
            aA2 = fmaf(f, u.z, aA2); aA3 = fmaf(f, u.w, aA3);
        }
        // ---- inter: aB = sum_j Q[t][j] * M[j][iq*4..] over j-half ----
        float aB0=0.f, aB1=0.f, aB2=0.f, aB3=0.f;
        #pragma unroll 8
        for (int j = hf*128; j < hf*128 + 128; j++) {
            float qv = sm[QS_OFF + t*257 + j];
            float4 m4 = *(const float4*)&sm[MS_OFF + j*12 + iq*4];
            aB0 = fmaf(qv, m4.x, aB0); aB1 = fmaf(qv, m4.y, aB1);
            aB2 = fmaf(qv, m4.z, aB2); aB3 = fmaf(qv, m4.w, aB3);
        }
        // weight partials: p = Gamma*inter + G*intra
        float4 G  = *(const float4*)&sm[GS_OFF  + t*8 + iq*4];
        float4 Ga = *(const float4*)&sm[GAS_OFF + t*8 + iq*4];
        float p0 = Ga.x*aB0 + G.x*aA0;
        float p1 = Ga.y*aB1 + G.y*aA1;
        float p2 = Ga.z*aB2 + G.z*aA2;
        float p3 = Ga.w*aB3 + G.w*aA3;
        if (hf) *(float4*)&sm[RED_OFF + t*8 + iq*4] = make_float4(p0, p1, p2, p3);
        __syncthreads();
        if (!hf) {
            float4 r   = *(const float4*)&sm[RED_OFF + t*8 + iq*4];
            float4 osc = *(const float4*)&sm[OS_OFF  + t*8 + iq*4];
            float rd   = sm[DEN_OFF + t];
            float4 o;
            o.x = osc.x * (p0 + r.x) * rd;
            o.y = osc.y * (p1 + r.y) * rd;
            o.z = osc.z * (p2 + r.z) * rd;
            o.w = osc.w * (p3 + r.w) * rd;
            *(float4*)&out[bB + (size_t)(t0 + t)*Dd + rowBase + iq*4] = o;
        }

        // ---- M update: M[j][i] = dec[i]*M[j][i] + esc[i]*sum_s U[s][i]*K[s][j]
        {
            int j = tid;
            float ac0=0.f,ac1=0.f,ac2=0.f,ac3=0.f,ac4=0.f,ac5=0.f,ac6=0.f,ac7=0.f;
            #pragma unroll 8
            for (int s = 0; s < 64; s++) {
                float kv = sm[KS_OFF + s*257 + j];
                float4 ua = *(const float4*)&sm[US_OFF + s*8];
                float4 ub = *(const float4*)&sm[US_OFF + s*8 + 4];
                ac0 = fmaf(kv, ua.x, ac0); ac1 = fmaf(kv, ua.y, ac1);
                ac2 = fmaf(kv, ua.z, ac2); ac3 = fmaf(kv, ua.w, ac3);
                ac4 = fmaf(kv, ub.x, ac4); ac5 = fmaf(kv, ub.y, ac5);
                ac6 = fmaf(kv, ub.z, ac6); ac7 = fmaf(kv, ub.w, ac7);
            }
            float4 d0 = *(const float4*)&sm[DEC_OFF];
            float4 d1 = *(const float4*)&sm[DEC_OFF + 4];
            float4 e0 = *(const float4*)&sm[ESC_OFF];
            float4 e1 = *(const float4*)&sm[ESC_OFF + 4];
            float4 m0 = *(const float4*)&sm[MS_OFF + j*12];
            float4 m1 = *(const float4*)&sm[MS_OFF + j*12 + 4];
            m0.x = d0.x*m0.x + e0.x*ac0;  m0.y = d0.y*m0.y + e0.y*ac1;
            m0.z = d0.z*m0.z + e0.z*ac2;  m0.w = d0.w*m0.w + e0.w*ac3;
            m1.x = d1.x*m1.x + e1.x*ac4;  m1.y = d1.y*m1.y + e1.y*ac5;
            m1.z = d1.z*m1.z + e1.z*ac6;  m1.w = d1.w*m1.w + e1.w*ac7;
            *(float4*)&sm[MS_OFF + j*12]     = m0;
            *(float4*)&sm[MS_OFF + j*12 + 4] = m1;
        }
    }
}

// ---------------------------------------------------------------------------
// Kernel 7: RMSNorm in place
// ---------------------------------------------------------------------------
__global__ __launch_bounds__(256) void rmsnorm_kernel(float* __restrict__ out,
                                                      const float* __restrict__ ns)
{
    const int gw   = blockIdx.x * 8 + (threadIdx.x >> 5);
    const int lane = threadIdx.x & 31;
    size_t base = (size_t)gw * Dd + lane * 8;
    float4 a = *(const float4*)&out[base];
    float4 c = *(const float4*)&out[base + 4];
    float ss = a.x*a.x + a.y*a.y + a.z*a.z + a.w*a.w
             + c.x*c.x + c.y*c.y + c.z*c.z + c.w*c.w;
    #pragma unroll
    for (int o = 16; o; o >>= 1) ss += __shfl_xor_sync(0xffffffffu, ss, o);
    float rinv = rsqrtf(ss * (1.0f / Dd) + 1e-8f);
    float4 s1 = *(const float4*)&ns[lane * 8];
    float4 s2 = *(const float4*)&ns[lane * 8 + 4];
    a.x *= rinv * s1.x; a.y *= rinv * s1.y; a.z *= rinv * s1.z; a.w *= rinv * s1.w;
    c.x *= rinv * s2.x; c.y *= rinv * s2.y; c.z *= rinv * s2.z; c.w *= rinv * s2.w;
    *(float4*)&out[base]     = a;
    *(float4*)&out[base + 4] = c;
}

// ---------------------------------------------------------------------------
extern "C" void kernel_launch(void* const* d_in, const int* in_sizes, int n_in,
                              void* d_out, int out_size)
{
    const float* x  = (const float*)d_in[0];
    const float* Wq = (const float*)d_in[1];
    const float* bq = (const float*)d_in[2];
    const float* Wk = (const float*)d_in[3];
    const float* bk = (const float*)d_in[4];
    const float* Wv = (const float*)d_in[5];
    const float* bv = (const float*)d_in[6];
    const float* Wg = (const float*)d_in[7];
    const float* bg = (const float*)d_in[8];
    const float* ib = (const float*)d_in[9];
    const float* ns = (const float*)d_in[10];
    float* out = (float*)d_out;

    cudaFuncSetAttribute(chunk_scan, cudaFuncAttributeMaxDynamicSharedMemorySize, SM_BYTES);

    dim3 ggrid(24, 128);
    proj_gemm<<<ggrid, 256>>>(x, Wq, bq, Wk, bk, Wv, bv, Wg, bg, ib);
    chan_scan<<<32, 32>>>();
    prep_kernel<<<BTD/4/256, 256>>>();
    score_kernel<<<128, 256>>>();
    denom_kernel<<<1024, 256>>>();
    chunk_scan<<<128, 256, SM_BYTES>>>(out);
    rmsnorm_kernel<<<1024, 256>>>(out, ns);
}

// round 5
// speedup vs baseline: 2.5995x; 1.0808x over previous
#include <cuda_runtime.h>
#include <math.h>

#define Bb 4
#define Tt 2048
#define Dd 256
#define BT (Bb*Tt)
#define BTD (Bb*Tt*Dd)
#define CC 64
#define NC 32
#define NCH 33

// Scratch (static __device__ — no allocations allowed)
__device__ float g_q[BTD];
__device__ float g_k[BTD];            // scaled by 1/sqrt(D)
__device__ float g_v[BTD];            // -> U after prep
__device__ float g_li[BTD];           // log_i -> E=li-b (chan) -> Gamma (prep)
__device__ float g_lf[BTD];           // log_f -> b-m (chan)   -> G     (prep)
__device__ float g_o[BTD];            // o_pre -> sigmoid(o) (prep)
__device__ float g_n[BTD];
__device__ float g_den[BT];
__device__ float g_S[Bb*NC*CC*CC];    // masked scores S[s][t]
__device__ float g_m[Bb*NCH*Dd];      // m at chunk starts + final
__device__ float g_bend[Bb*NC*Dd];

// ---------------------------------------------------------------------------
// tf32 helpers
// ---------------------------------------------------------------------------
__device__ __forceinline__ unsigned f2tf32(float x) {
    unsigned r;
    asm("cvt.rna.tf32.f32 %0, %1;" : "=r"(r) : "f"(x));
    return r;
}
__device__ __forceinline__ void mma_tf32(float* d,
    const unsigned* a, const unsigned* b)
{
    asm volatile(
        "mma.sync.aligned.m16n8k8.row.col.f32.tf32.tf32.f32 "
        "{%0,%1,%2,%3}, {%4,%5,%6,%7}, {%8,%9}, {%0,%1,%2,%3};"
        : "+f"(d[0]), "+f"(d[1]), "+f"(d[2]), "+f"(d[3])
        : "r"(a[0]), "r"(a[1]), "r"(a[2]), "r"(a[3]),
          "r"(b[0]), "r"(b[1]));
}
__device__ __forceinline__ void cpa16(void* sm, const void* g) {
    unsigned s = (unsigned)__cvta_generic_to_shared(sm);
    asm volatile("cp.async.ca.shared.global [%0], [%1], 16;" :: "r"(s), "l"(g));
}

// ---------------------------------------------------------------------------
// Kernel 1: projection GEMM (8192 x 1536 x 256) via 3xTF32 mma.sync
// CTA tile 128x64, 8 warps of 32x32, k-tile 16, double-buffered cp.async.
// ---------------------------------------------------------------------------
#define AS_STRIDE 20
#define BS_STRIDE 72

__global__ __launch_bounds__(256, 2) void proj_gemm(
    const float* __restrict__ x,
    const float* __restrict__ Wq, const float* __restrict__ bq,
    const float* __restrict__ Wk, const float* __restrict__ bk,
    const float* __restrict__ Wv, const float* __restrict__ bv,
    const float* __restrict__ Wg, const float* __restrict__ bg,
    const float* __restrict__ ib)
{
    __shared__ float As[2][128 * AS_STRIDE];
    __shared__ float Bs[2][16 * BS_STRIDE];

    const int tid  = threadIdx.x;
    const int warp = tid >> 5, lane = tid & 31;
    const int g    = lane >> 2, q = lane & 3;
    const int wm   = (warp >> 1) * 32;
    const int wn   = (warp & 1) * 32;

    const int mBase = blockIdx.y * 128;
    const int nBase = blockIdx.x * 64;

    const float* W;  const float* bias;  float* outArr;
    int ldw, colW, outCol, mode;
    if (nBase < 256)      { W = Wq; ldw = 256; colW = nBase;       bias = bq; outArr = g_q;  mode = 0; }
    else if (nBase < 512) { W = Wk; ldw = 256; colW = nBase - 256; bias = bk; outArr = g_k;  mode = 1; }
    else if (nBase < 768) { W = Wv; ldw = 256; colW = nBase - 512; bias = bv; outArr = g_v;  mode = 0; }
    else {
        W = Wg; ldw = 768; colW = nBase - 768; bias = bg;
        int gi = colW >> 8;
        outArr = (gi == 0) ? g_li : ((gi == 1) ? g_lf : g_o);
        mode   = (gi == 0) ? 2 : ((gi == 1) ? 3 : 0);
    }
    outCol = (nBase < 768) ? colW : (colW & 255);

    auto issue = [&](int kt, int st) {
        const int c0 = kt * 16;
        #pragma unroll
        for (int h = 0; h < 2; h++) {
            int idx = tid + h * 256;
            int r = idx >> 2, cc = (idx & 3) * 4;
            cpa16(&As[st][r * AS_STRIDE + cc],
                  x + (size_t)(mBase + r) * 256 + c0 + cc);
        }
        {
            int k = tid >> 4, n4 = (tid & 15) * 4;
            cpa16(&Bs[st][k * BS_STRIDE + n4],
                  W + (size_t)(c0 + k) * ldw + colW + n4);
        }
    };

    float acc[2][4][4];
    #pragma unroll
    for (int mf = 0; mf < 2; mf++)
        #pragma unroll
        for (int nf = 0; nf < 4; nf++)
            #pragma unroll
            for (int r = 0; r < 4; r++) acc[mf][nf][r] = 0.0f;

    issue(0, 0);
    asm volatile("cp.async.commit_group;");

    for (int kt = 0; kt < 16; kt++) {
        const int st = kt & 1;
        if (kt < 15) {
            issue(kt + 1, st ^ 1);
            asm volatile("cp.async.commit_group;");
            asm volatile("cp.async.wait_group 1;");
        } else {
            asm volatile("cp.async.wait_group 0;");
        }
        __syncthreads();

        const float* A_ = As[st];
        const float* B_ = Bs[st];

        #pragma unroll
        for (int ks = 0; ks < 2; ks++) {
            const int kk = ks * 8;
            unsigned ah[2][4], al[2][4];
            #pragma unroll
            for (int mf = 0; mf < 2; mf++) {
                int r0 = wm + mf * 16 + g;
                float f0 = A_[r0 * AS_STRIDE + kk + q];
                float f1 = A_[(r0 + 8) * AS_STRIDE + kk + q];
                float f2 = A_[r0 * AS_STRIDE + kk + q + 4];
                float f3 = A_[(r0 + 8) * AS_STRIDE + kk + q + 4];
                ah[mf][0] = f2tf32(f0); al[mf][0] = f2tf32(f0 - __uint_as_float(ah[mf][0]));
                ah[mf][1] = f2tf32(f1); al[mf][1] = f2tf32(f1 - __uint_as_float(ah[mf][1]));
                ah[mf][2] = f2tf32(f2); al[mf][2] = f2tf32(f2 - __uint_as_float(ah[mf][2]));
                ah[mf][3] = f2tf32(f3); al[mf][3] = f2tf32(f3 - __uint_as_float(ah[mf][3]));
            }
            unsigned bh[4][2], bl[4][2];
            #pragma unroll
            for (int nf = 0; nf < 4; nf++) {
                int cN = wn + nf * 8 + g;
                float f0 = B_[(kk + q) * BS_STRIDE + cN];
                float f1 = B_[(kk + q + 4) * BS_STRIDE + cN];
                bh[nf][0] = f2tf32(f0); bl[nf][0] = f2tf32(f0 - __uint_as_float(bh[nf][0]));
                bh[nf][1] = f2tf32(f1); bl[nf][1] = f2tf32(f1 - __uint_as_float(bh[nf][1]));
            }
            #pragma unroll
            for (int mf = 0; mf < 2; mf++)
                #pragma unroll
                for (int nf = 0; nf < 4; nf++) {
                    mma_tf32(acc[mf][nf], ah[mf], bh[nf]);
                    mma_tf32(acc[mf][nf], ah[mf], bl[nf]);
                    mma_tf32(acc[mf][nf], al[mf], bh[nf]);
                }
        }
        __syncthreads();
    }

    // Epilogue: bias + per-segment activation, float2 stores
    #pragma unroll
    for (int mf = 0; mf < 2; mf++) {
        int row0 = mBase + wm + mf * 16 + g;
        #pragma unroll
        for (int nf = 0; nf < 4; nf++) {
            int nl = wn + nf * 8 + 2 * q;        // local col within 64-tile
            float vals[4] = { acc[mf][nf][0], acc[mf][nf][1],
                              acc[mf][nf][2], acc[mf][nf][3] };
            #pragma unroll
            for (int e = 0; e < 4; e++) {
                int cl = nl + (e & 1);
                float val = vals[e] + bias[colW + cl];
                if (mode == 1) {
                    val *= 0.0625f;
                } else if (mode == 2) {
                    val += ib[outCol + cl];
                    val = 10.0f * tanhf(val * 0.1f);
                } else if (mode == 3) {
                    val = -(fmaxf(val, 0.0f) + log1pf(__expf(-fabsf(val))));
                }
                vals[e] = val;
            }
            int row1 = row0 + 8;
            *(float2*)&outArr[(size_t)row0 * 256 + outCol + nl] = make_float2(vals[0], vals[1]);
            *(float2*)&outArr[(size_t)row1 * 256 + outCol + nl] = make_float2(vals[2], vals[3]);
        }
    }
}

// ---------------------------------------------------------------------------
// Kernel 2: per-channel scan: m, n; writes E=li-b, bm=b-m, bend, m boundaries
// ---------------------------------------------------------------------------
__global__ __launch_bounds__(32) void chan_scan()
{
    const int b = blockIdx.x >> 3;
    const int d = ((blockIdx.x & 7) << 5) + threadIdx.x;
    size_t base = (size_t)b * Tt * Dd + d;
    float m = 0.0f, n = 0.0f;

    for (int c = 0; c < NC; c++) {
        g_m[(size_t)((b*NCH + c) << 8) + d] = m;
        float bl = 0.0f;
        size_t cb = base + (size_t)c * CC * Dd;
        for (int g = 0; g < CC; g += 8) {
            float li[8], lf[8], kk[8];
            #pragma unroll
            for (int u = 0; u < 8; u++) {
                size_t idx = cb + (size_t)(g + u) * Dd;
                li[u] = g_li[idx]; lf[u] = g_lf[idx]; kk[u] = g_k[idx];
            }
            #pragma unroll
            for (int u = 0; u < 8; u++) {
                size_t idx = cb + (size_t)(g + u) * Dd;
                bl += lf[u];
                float mn = fmaxf(lf[u] + m, li[u]);
                float is = __expf(li[u] - mn);
                float fs = __expf(lf[u] + m - mn);
                n = fmaf(fs, n, is * kk[u]);
                g_n[idx]  = n;
                g_li[idx] = li[u] - bl;
                g_lf[idx] = bl - mn;
                m = mn;
            }
        }
        g_bend[(size_t)((b*NC + c) << 8) + d] = bl;
    }
    g_m[(size_t)((b*NCH + NC) << 8) + d] = m;
}

// ---------------------------------------------------------------------------
// Kernel 3: elementwise prep: U, G, Gamma, sigmoid(o)
// ---------------------------------------------------------------------------
__global__ __launch_bounds__(256) void prep_kernel()
{
    int i4 = blockIdx.x * 256 + threadIdx.x;   // BTD/4 float4 slots
    int d4 = i4 & 63;
    int t  = (i4 >> 6) & 2047;
    int b  = i4 >> 17;
    int c  = t >> 6;

    float4 E  = ((const float4*)g_li)[i4];
    float4 bm = ((const float4*)g_lf)[i4];
    float4 v  = ((const float4*)g_v)[i4];
    float4 op = ((const float4*)g_o)[i4];
    float4 be = ((const float4*)g_bend)[(size_t)(b*NC + c)*64 + d4];
    float4 mp = ((const float4*)g_m)[(size_t)(b*NCH + c)*64 + d4];

    float4 U, G, Ga, sg;
    U.x = __expf(E.x + be.x) * v.x;  U.y = __expf(E.y + be.y) * v.y;
    U.z = __expf(E.z + be.z) * v.z;  U.w = __expf(E.w + be.w) * v.w;
    G.x = __expf(bm.x - be.x); G.y = __expf(bm.y - be.y);
    G.z = __expf(bm.z - be.z); G.w = __expf(bm.w - be.w);
    Ga.x = __expf(bm.x + mp.x); Ga.y = __expf(bm.y + mp.y);
    Ga.z = __expf(bm.z + mp.z); Ga.w = __expf(bm.w + mp.w);
    sg.x = 1.0f/(1.0f + __expf(-op.x)); sg.y = 1.0f/(1.0f + __expf(-op.y));
    sg.z = 1.0f/(1.0f + __expf(-op.z)); sg.w = 1.0f/(1.0f + __expf(-op.w));

    ((float4*)g_v)[i4]  = U;
    ((float4*)g_lf)[i4] = G;
    ((float4*)g_li)[i4] = Ga;
    ((float4*)g_o)[i4]  = sg;
}

// ---------------------------------------------------------------------------
// Kernel 4: denom[b,t] = max(|n_t . q_t|, 1e-6)
// ---------------------------------------------------------------------------
__global__ __launch_bounds__(256) void denom_kernel()
{
    const int gw   = blockIdx.x * 8 + (threadIdx.x >> 5);
    const int lane = threadIdx.x & 31;
    size_t base = (size_t)gw * Dd + lane * 8;
    float4 n1 = *(const float4*)&g_n[base];
    float4 n2 = *(const float4*)&g_n[base + 4];
    float4 q1 = *(const float4*)&g_q[base];
    float4 q2 = *(const float4*)&g_q[base + 4];
    float s = n1.x*q1.x + n1.y*q1.y + n1.z*q1.z + n1.w*q1.w
            + n2.x*q2.x + n2.y*q2.y + n2.z*q2.z + n2.w*q2.w;
    #pragma unroll
    for (int o = 16; o; o >>= 1) s += __shfl_xor_sync(0xffffffffu, s, o);
    if (lane == 0) g_den[gw] = fmaxf(fabsf(s), 1e-6f);
}

// ---------------------------------------------------------------------------
// Kernel 5: per-chunk scores S[s][t] = k_s . q_t  masked (s<=t)
// ---------------------------------------------------------------------------
__global__ __launch_bounds__(256) void score_kernel()
{
    const int b = blockIdx.x >> 5, c = blockIdx.x & 31;
    __shared__ float Qs[64][33];
    __shared__ float Ks[64][33];
    const int tid = threadIdx.x;
    const int sg = tid >> 4, tg = tid & 15;
    float acc[4][4] = {};
    size_t base = ((size_t)b * Tt + c * CC) * Dd;

    for (int db = 0; db < 256; db += 32) {
        __syncthreads();
        for (int l = tid; l < 512; l += 256) {
            int r = l >> 3, q4 = (l & 7) * 4;
            float4 qv = *(const float4*)&g_q[base + (size_t)r*Dd + db + q4];
            float4 kv = *(const float4*)&g_k[base + (size_t)r*Dd + db + q4];
            Qs[r][q4+0]=qv.x; Qs[r][q4+1]=qv.y; Qs[r][q4+2]=qv.z; Qs[r][q4+3]=qv.w;
            Ks[r][q4+0]=kv.x; Ks[r][q4+1]=kv.y; Ks[r][q4+2]=kv.z; Ks[r][q4+3]=kv.w;
        }
        __syncthreads();
        #pragma unroll 8
        for (int dd = 0; dd < 32; dd++) {
            float kv[4], qv[4];
            #pragma unroll
            for (int x = 0; x < 4; x++) { kv[x] = Ks[sg*4+x][dd]; qv[x] = Qs[tg*4+x][dd]; }
            #pragma unroll
            for (int si = 0; si < 4; si++)
                #pragma unroll
                for (int ti = 0; ti < 4; ti++)
                    acc[si][ti] = fmaf(kv[si], qv[ti], acc[si][ti]);
        }
    }

    float* Sp = g_S + (size_t)(b*NC + c) * (CC*CC);
    #pragma unroll
    for (int si = 0; si < 4; si++) {
        int s = sg*4 + si;
        #pragma unroll
        for (int ti = 0; ti < 4; ti++) {
            int t = tg*4 + ti;
            Sp[s*64 + t] = (s <= t) ? acc[si][ti] : 0.0f;
        }
    }
}

// ---------------------------------------------------------------------------
// Kernel 6: chunk scan. CTA = (batch, 8-row block). 32 sequential chunks.
// ---------------------------------------------------------------------------
#define QS_OFF   0            // [64][257]
#define KS_OFF   16448        // [64][257]
#define SS_OFF   32896        // [64][64]
#define MS_OFF   36992        // [256][12] (8 used)
#define US_OFF   40064        // [64][8]  U
#define GS_OFF   40576        // [64][8]  G
#define GAS_OFF  41088        // [64][8]  Gamma
#define OS_OFF   41600        // [64][8]  sigmoid(o)
#define DEN_OFF  42112        // [64] reciprocal den
#define DEC_OFF  42176        // [8]
#define ESC_OFF  42184        // [8]
#define RED_OFF  42192        // [512]
#define SM_FLOATS 42704
#define SM_BYTES  (SM_FLOATS*4)

__global__ __launch_bounds__(256) void chunk_scan(float* __restrict__ out)
{
    extern __shared__ float sm[];
    const int tid = threadIdx.x;
    const int b = blockIdx.x >> 5, rb = blockIdx.x & 31;
    const int rowBase = rb * 8;
    const size_t bB = (size_t)b * Tt * Dd;

    {
        int j = tid;
        *(float4*)&sm[MS_OFF + j*12]     = make_float4(0.f,0.f,0.f,0.f);
        *(float4*)&sm[MS_OFF + j*12 + 4] = make_float4(0.f,0.f,0.f,0.f);
    }

    const int t  = tid & 63;
    const int iq = (tid >> 6) & 1;
    const int hf = tid >> 7;

    for (int c = 0; c < NC; c++) {
        const int t0 = c * CC;
        __syncthreads();

        for (int p = tid; p < 8192; p += 256) {
            int arr = p >> 12;
            int idx = p & 4095;
            int r = idx >> 6, c4 = (idx & 63) * 4;
            const float* src = arr ? g_k : g_q;
            float4 v = *(const float4*)&src[bB + (size_t)(t0 + r)*Dd + c4];
            float* dst = &sm[(arr ? KS_OFF : QS_OFF) + r*257 + c4];
            dst[0]=v.x; dst[1]=v.y; dst[2]=v.z; dst[3]=v.w;
        }
        {
            const float4* Sg = (const float4*)(g_S + (size_t)(b*NC + c)*(CC*CC));
            for (int p = tid; p < 1024; p += 256)
                *(float4*)&sm[SS_OFF + p*4] = Sg[p];
        }
        for (int p = tid; p < 512; p += 256) {
            int arr = p >> 7, idx = p & 127;
            int s = idx >> 1, hh = (idx & 1) * 4;
            const float* src = (arr==0) ? g_v : (arr==1) ? g_lf : (arr==2) ? g_li : g_o;
            float4 v = *(const float4*)&src[bB + (size_t)(t0 + s)*Dd + rowBase + hh];
            *(float4*)&sm[US_OFF + arr*512 + s*8 + hh] = v;
        }
        if (tid < 64) sm[DEN_OFF + tid] = 1.0f / g_den[(size_t)b*Tt + t0 + tid];
        if (tid < 8) {
            float be = g_bend[(size_t)(b*NC + c)*Dd + rowBase + tid];
            float mp = g_m[(size_t)(b*NCH + c)*Dd + rowBase + tid];
            float me = g_m[(size_t)(b*NCH + c + 1)*Dd + rowBase + tid];
            sm[DEC_OFF + tid] = __expf(be + mp - me);
            sm[ESC_OFF + tid] = __expf(-me);
        }
        __syncthreads();

        float aA0=0.f, aA1=0.f, aA2=0.f, aA3=0.f;
        #pragma unroll 8
        for (int s = hf*32; s < hf*32 + 32; s++) {
            float f = sm[SS_OFF + s*64 + t];
            float4 u = *(const float4*)&sm[US_OFF + s*8 + iq*4];
            aA0 = fmaf(f, u.x, aA0); aA1 = fmaf(f, u.y, aA1);
            aA2 = fmaf(f, u.z, aA2); aA3 = fmaf(f, u.w, aA3);
        }
        float aB0=0.f, aB1=0.f, aB2=0.f, aB3=0.f;
        #pragma unroll 8
        for (int j = hf*128; j < hf*128 + 128; j++) {
            float qv = sm[QS_OFF + t*257 + j];
            float4 m4 = *(const float4*)&sm[MS_OFF + j*12 + iq*4];
            aB0 = fmaf(qv, m4.x, aB0); aB1 = fmaf(qv, m4.y, aB1);
            aB2 = fmaf(qv, m4.z, aB2); aB3 = fmaf(qv, m4.w, aB3);
        }
        float4 G  = *(const float4*)&sm[GS_OFF  + t*8 + iq*4];
        float4 Ga = *(const float4*)&sm[GAS_OFF + t*8 + iq*4];
        float p0 = Ga.x*aB0 + G.x*aA0;
        float p1 = Ga.y*aB1 + G.y*aA1;
        float p2 = Ga.z*aB2 + G.z*aA2;
        float p3 = Ga.w*aB3 + G.w*aA3;
        if (hf) *(float4*)&sm[RED_OFF + t*8 + iq*4] = make_float4(p0, p1, p2, p3);
        __syncthreads();
        if (!hf) {
            float4 r   = *(const float4*)&sm[RED_OFF + t*8 + iq*4];
            float4 osc = *(const float4*)&sm[OS_OFF  + t*8 + iq*4];
            float rd   = sm[DEN_OFF + t];
            float4 o;
            o.x = osc.x * (p0 + r.x) * rd;
            o.y = osc.y * (p1 + r.y) * rd;
            o.z = osc.z * (p2 + r.z) * rd;
            o.w = osc.w * (p3 + r.w) * rd;
            *(float4*)&out[bB + (size_t)(t0 + t)*Dd + rowBase + iq*4] = o;
        }

        {
            int j = tid;
            float ac0=0.f,ac1=0.f,ac2=0.f,ac3=0.f,ac4=0.f,ac5=0.f,ac6=0.f,ac7=0.f;
            #pragma unroll 8
            for (int s = 0; s < 64; s++) {
                float kv = sm[KS_OFF + s*257 + j];
                float4 ua = *(const float4*)&sm[US_OFF + s*8];
                float4 ub = *(const float4*)&sm[US_OFF + s*8 + 4];
                ac0 = fmaf(kv, ua.x, ac0); ac1 = fmaf(kv, ua.y, ac1);
                ac2 = fmaf(kv, ua.z, ac2); ac3 = fmaf(kv, ua.w, ac3);
                ac4 = fmaf(kv, ub.x, ac4); ac5 = fmaf(kv, ub.y, ac5);
                ac6 = fmaf(kv, ub.z, ac6); ac7 = fmaf(kv, ub.w, ac7);
            }
            float4 d0 = *(const float4*)&sm[DEC_OFF];
            float4 d1 = *(const float4*)&sm[DEC_OFF + 4];
            float4 e0 = *(const float4*)&sm[ESC_OFF];
            float4 e1 = *(const float4*)&sm[ESC_OFF + 4];
            float4 m0 = *(const float4*)&sm[MS_OFF + j*12];
            float4 m1 = *(const float4*)&sm[MS_OFF + j*12 + 4];
            m0.x = d0.x*m0.x + e0.x*ac0;  m0.y = d0.y*m0.y + e0.y*ac1;
            m0.z = d0.z*m0.z + e0.z*ac2;  m0.w = d0.w*m0.w + e0.w*ac3;
            m1.x = d1.x*m1.x + e1.x*ac4;  m1.y = d1.y*m1.y + e1.y*ac5;
            m1.z = d1.z*m1.z + e1.z*ac6;  m1.w = d1.w*m1.w + e1.w*ac7;
            *(float4*)&sm[MS_OFF + j*12]     = m0;
            *(float4*)&sm[MS_OFF + j*12 + 4] = m1;
        }
    }
}

// ---------------------------------------------------------------------------
// Kernel 7: RMSNorm in place
// ---------------------------------------------------------------------------
__global__ __launch_bounds__(256) void rmsnorm_kernel(float* __restrict__ out,
                                                      const float* __restrict__ ns)
{
    const int gw   = blockIdx.x * 8 + (threadIdx.x >> 5);
    const int lane = threadIdx.x & 31;
    size_t base = (size_t)gw * Dd + lane * 8;
    float4 a = *(const float4*)&out[base];
    float4 c = *(const float4*)&out[base + 4];
    float ss = a.x*a.x + a.y*a.y + a.z*a.z + a.w*a.w
             + c.x*c.x + c.y*c.y + c.z*c.z + c.w*c.w;
    #pragma unroll
    for (int o = 16; o; o >>= 1) ss += __shfl_xor_sync(0xffffffffu, ss, o);
    float rinv = rsqrtf(ss * (1.0f / Dd) + 1e-8f);
    float4 s1 = *(const float4*)&ns[lane * 8];
    float4 s2 = *(const float4*)&ns[lane * 8 + 4];
    a.x *= rinv * s1.x; a.y *= rinv * s1.y; a.z *= rinv * s1.z; a.w *= rinv * s1.w;
    c.x *= rinv * s2.x; c.y *= rinv * s2.y; c.z *= rinv * s2.z; c.w *= rinv * s2.w;
    *(float4*)&out[base]     = a;
    *(float4*)&out[base + 4] = c;
}

// ---------------------------------------------------------------------------
extern "C" void kernel_launch(void* const* d_in, const int* in_sizes, int n_in,
                              void* d_out, int out_size)
{
    const float* x  = (const float*)d_in[0];
    const float* Wq = (const float*)d_in[1];
    const float* bq = (const float*)d_in[2];
    const float* Wk = (const float*)d_in[3];
    const float* bk = (const float*)d_in[4];
    const float* Wv = (const float*)d_in[5];
    const float* bv = (const float*)d_in[6];
    const float* Wg = (const float*)d_in[7];
    const float* bg = (const float*)d_in[8];
    const float* ib = (const float*)d_in[9];
    const float* ns = (const float*)d_in[10];
    float* out = (float*)d_out;

    cudaFuncSetAttribute(chunk_scan, cudaFuncAttributeMaxDynamicSharedMemorySize, SM_BYTES);

    dim3 ggrid(24, 64);   // N tiles (64) x M tiles (128)
    proj_gemm<<<ggrid, 256>>>(x, Wq, bq, Wk, bk, Wv, bv, Wg, bg, ib);
    chan_scan<<<32, 32>>>();
    prep_kernel<<<BTD/4/256, 256>>>();
    score_kernel<<<128, 256>>>();
    denom_kernel<<<1024, 256>>>();
    chunk_scan<<<128, 256, SM_BYTES>>>(out);
    rmsnorm_kernel<<<1024, 256>>>(out, ns);
}

// round 6
// speedup vs baseline: 5.1672x; 1.9877x over previous
#include <cuda_runtime.h>
#include <math.h>

#define Bb 4
#define Tt 2048
#define Dd 256
#define BT (Bb*Tt)
#define BTD (Bb*Tt*Dd)
#define CC 64
#define NC 32
#define NCH 33

// Scratch (static __device__ — no allocations allowed)
__device__ float g_q[BTD];
__device__ float g_k[BTD];            // scaled by 1/sqrt(D)
__device__ float g_v[BTD];            // -> U after prep
__device__ float g_li[BTD];           // log_i -> E=li-b (chanC) -> Gamma (prep)
__device__ float g_lf[BTD];           // log_f -> b-m (chanC)   -> G     (prep)
__device__ float g_o[BTD];            // o_pre -> sigmoid(o) (prep)
__device__ float g_n[BTD];
__device__ float g_den[BT];
__device__ float g_S[Bb*NC*CC*CC];    // masked scores S[s][t]
__device__ float g_m[Bb*NCH*Dd];      // m at chunk starts + final
__device__ float g_bend[Bb*NC*Dd];    // B (sum lf within chunk)
__device__ float g_L[Bb*NC*Dd];       // local max(li - b_t)
__device__ float g_P[Bb*NC*Dd];       // local sum exp(li - b_t) k
__device__ float g_nin[Bb*NC*Dd];     // n at chunk start
__device__ float g_M[(size_t)Bb*NC*Dd*Dd];  // chunk states [b][c][j][i]

// ---------------------------------------------------------------------------
// tf32 helpers
// ---------------------------------------------------------------------------
__device__ __forceinline__ unsigned f2tf32(float x) {
    unsigned r;
    asm("cvt.rna.tf32.f32 %0, %1;" : "=r"(r) : "f"(x));
    return r;
}
__device__ __forceinline__ void mma_tf32(float* d,
    const unsigned* a, const unsigned* b)
{
    asm volatile(
        "mma.sync.aligned.m16n8k8.row.col.f32.tf32.tf32.f32 "
        "{%0,%1,%2,%3}, {%4,%5,%6,%7}, {%8,%9}, {%0,%1,%2,%3};"
        : "+f"(d[0]), "+f"(d[1]), "+f"(d[2]), "+f"(d[3])
        : "r"(a[0]), "r"(a[1]), "r"(a[2]), "r"(a[3]),
          "r"(b[0]), "r"(b[1]));
}
__device__ __forceinline__ void cpa16(void* sm, const void* g) {
    unsigned s = (unsigned)__cvta_generic_to_shared(sm);
    asm volatile("cp.async.ca.shared.global [%0], [%1], 16;" :: "r"(s), "l"(g));
}

// ---------------------------------------------------------------------------
// Kernel 1: projection GEMM (8192 x 1536 x 256) via 3xTF32 mma.sync
// ---------------------------------------------------------------------------
#define AS_STRIDE 20
#define BS_STRIDE 72

__global__ __launch_bounds__(256, 2) void proj_gemm(
    const float* __restrict__ x,
    const float* __restrict__ Wq, const float* __restrict__ bq,
    const float* __restrict__ Wk, const float* __restrict__ bk,
    const float* __restrict__ Wv, const float* __restrict__ bv,
    const float* __restrict__ Wg, const float* __restrict__ bg,
    const float* __restrict__ ib)
{
    __shared__ float As[2][128 * AS_STRIDE];
    __shared__ float Bs[2][16 * BS_STRIDE];

    const int tid  = threadIdx.x;
    const int warp = tid >> 5, lane = tid & 31;
    const int g    = lane >> 2, q = lane & 3;
    const int wm   = (warp >> 1) * 32;
    const int wn   = (warp & 1) * 32;

    const int mBase = blockIdx.y * 128;
    const int nBase = blockIdx.x * 64;

    const float* W;  const float* bias;  float* outArr;
    int ldw, colW, outCol, mode;
    if (nBase < 256)      { W = Wq; ldw = 256; colW = nBase;       bias = bq; outArr = g_q;  mode = 0; }
    else if (nBase < 512) { W = Wk; ldw = 256; colW = nBase - 256; bias = bk; outArr = g_k;  mode = 1; }
    else if (nBase < 768) { W = Wv; ldw = 256; colW = nBase - 512; bias = bv; outArr = g_v;  mode = 0; }
    else {
        W = Wg; ldw = 768; colW = nBase - 768; bias = bg;
        int gi = colW >> 8;
        outArr = (gi == 0) ? g_li : ((gi == 1) ? g_lf : g_o);
        mode   = (gi == 0) ? 2 : ((gi == 1) ? 3 : 0);
    }
    outCol = (nBase < 768) ? colW : (colW & 255);

    auto issue = [&](int kt, int st) {
        const int c0 = kt * 16;
        #pragma unroll
        for (int h = 0; h < 2; h++) {
            int idx = tid + h * 256;
            int r = idx >> 2, cc = (idx & 3) << 2;
            cpa16(&As[st][r * AS_STRIDE + cc],
                  x + (size_t)(mBase + r) * 256 + c0 + cc);
        }
        {
            int k = tid >> 4, n4 = (tid & 15) << 2;
            cpa16(&Bs[st][k * BS_STRIDE + n4],
                  W + (size_t)(c0 + k) * ldw + colW + n4);
        }
    };

    float acc[2][4][4];
    #pragma unroll
    for (int mf = 0; mf < 2; mf++)
        #pragma unroll
        for (int nf = 0; nf < 4; nf++)
            #pragma unroll
            for (int r = 0; r < 4; r++) acc[mf][nf][r] = 0.0f;

    issue(0, 0);
    asm volatile("cp.async.commit_group;");

    for (int kt = 0; kt < 16; kt++) {
        const int st = kt & 1;
        if (kt < 15) {
            issue(kt + 1, st ^ 1);
            asm volatile("cp.async.commit_group;");
            asm volatile("cp.async.wait_group 1;");
        } else {
            asm volatile("cp.async.wait_group 0;");
        }
        __syncthreads();

        const float* A_ = As[st];
        const float* B_ = Bs[st];

        #pragma unroll
        for (int ks = 0; ks < 2; ks++) {
            const int kk = ks * 8;
            unsigned ah[2][4], al[2][4];
            #pragma unroll
            for (int mf = 0; mf < 2; mf++) {
                int r0 = wm + mf * 16 + g;
                float f0 = A_[r0 * AS_STRIDE + kk + q];
                float f1 = A_[(r0 + 8) * AS_STRIDE + kk + q];
                float f2 = A_[r0 * AS_STRIDE + kk + q + 4];
                float f3 = A_[(r0 + 8) * AS_STRIDE + kk + q + 4];
                ah[mf][0] = f2tf32(f0); al[mf][0] = f2tf32(f0 - __uint_as_float(ah[mf][0]));
                ah[mf][1] = f2tf32(f1); al[mf][1] = f2tf32(f1 - __uint_as_float(ah[mf][1]));
                ah[mf][2] = f2tf32(f2); al[mf][2] = f2tf32(f2 - __uint_as_float(ah[mf][2]));
                ah[mf][3] = f2tf32(f3); al[mf][3] = f2tf32(f3 - __uint_as_float(ah[mf][3]));
            }
            unsigned bh[4][2], bl[4][2];
            #pragma unroll
            for (int nf = 0; nf < 4; nf++) {
                int cN = wn + nf * 8 + g;
                float f0 = B_[(kk + q) * BS_STRIDE + cN];
                float f1 = B_[(kk + q + 4) * BS_STRIDE + cN];
                bh[nf][0] = f2tf32(f0); bl[nf][0] = f2tf32(f0 - __uint_as_float(bh[nf][0]));
                bh[nf][1] = f2tf32(f1); bl[nf][1] = f2tf32(f1 - __uint_as_float(bh[nf][1]));
            }
            #pragma unroll
            for (int mf = 0; mf < 2; mf++)
                #pragma unroll
                for (int nf = 0; nf < 4; nf++) {
                    mma_tf32(acc[mf][nf], ah[mf], bh[nf]);
                    mma_tf32(acc[mf][nf], ah[mf], bl[nf]);
                    mma_tf32(acc[mf][nf], al[mf], bh[nf]);
                }
        }
        __syncthreads();
    }

    #pragma unroll
    for (int mf = 0; mf < 2; mf++) {
        int row0 = mBase + wm + mf * 16 + g;
        #pragma unroll
        for (int nf = 0; nf < 4; nf++) {
            int nl = wn + nf * 8 + 2 * q;
            float vals[4] = { acc[mf][nf][0], acc[mf][nf][1],
                              acc[mf][nf][2], acc[mf][nf][3] };
            #pragma unroll
            for (int e = 0; e < 4; e++) {
                int cl = nl + (e & 1);
                float val = vals[e] + bias[colW + cl];
                if (mode == 1) {
                    val *= 0.0625f;
                } else if (mode == 2) {
                    val += ib[outCol + cl];
                    val = 10.0f * tanhf(val * 0.1f);
                } else if (mode == 3) {
                    val = -(fmaxf(val, 0.0f) + log1pf(__expf(-fabsf(val))));
                }
                vals[e] = val;
            }
            int row1 = row0 + 8;
            *(float2*)&outArr[(size_t)row0 * 256 + outCol + nl] = make_float2(vals[0], vals[1]);
            *(float2*)&outArr[(size_t)row1 * 256 + outCol + nl] = make_float2(vals[2], vals[3]);
        }
    }
}

// ---------------------------------------------------------------------------
// chan phase A: per (b,c,d) local chunk reductions: B=sum lf, L=max(li-b), P
// ---------------------------------------------------------------------------
__global__ __launch_bounds__(256) void chanA()
{
    const int bc = blockIdx.x;             // b*NC + c
    const int d  = threadIdx.x;
    const int b  = bc >> 5, c = bc & 31;
    size_t base = (size_t)b * Tt * Dd + (size_t)c * CC * Dd + d;

    float bl = 0.0f, L = -1e30f, P = 0.0f;
    for (int g = 0; g < CC; g += 8) {
        float li[8], lf[8], kk[8];
        #pragma unroll
        for (int u = 0; u < 8; u++) {
            size_t idx = base + (size_t)(g + u) * Dd;
            li[u] = g_li[idx]; lf[u] = g_lf[idx]; kk[u] = g_k[idx];
        }
        #pragma unroll
        for (int u = 0; u < 8; u++) {
            bl += lf[u];
            float e = li[u] - bl;
            L = fmaxf(L, e);
            P = fmaf(__expf(e), kk[u], P);
        }
    }
    g_bend[(size_t)bc * Dd + d] = bl;
    g_L[(size_t)bc * Dd + d]    = L;
    g_P[(size_t)bc * Dd + d]    = P;
}

// ---------------------------------------------------------------------------
// chan phase B: sequential stitch over 32 chunks (1024 threads total)
// ---------------------------------------------------------------------------
__global__ __launch_bounds__(256) void chanB()
{
    const int b = blockIdx.x, d = threadIdx.x;
    float m = 0.0f, n = 0.0f;
    for (int c = 0; c < NC; c++) {
        g_m[(size_t)(b*NCH + c) * Dd + d]  = m;
        g_nin[(size_t)(b*NC + c) * Dd + d] = n;
        float B = g_bend[(size_t)(b*NC + c) * Dd + d];
        float L = g_L[(size_t)(b*NC + c) * Dd + d];
        float P = g_P[(size_t)(b*NC + c) * Dd + d];
        float me = B + fmaxf(m, L);
        n = __expf(B + m - me) * n + __expf(B - me) * P;
        m = me;
    }
    g_m[(size_t)(b*NCH + NC) * Dd + d] = m;
}

// ---------------------------------------------------------------------------
// chan phase C: per (b,c,d) finalize: E=li-b, bm=b-m, n_t
// ---------------------------------------------------------------------------
__global__ __launch_bounds__(256) void chanC()
{
    const int bc = blockIdx.x;
    const int d  = threadIdx.x;
    const int b  = bc >> 5, c = bc & 31;
    size_t base = (size_t)b * Tt * Dd + (size_t)c * CC * Dd + d;

    const float m_in = g_m[(size_t)(b*NCH + c) * Dd + d];
    const float n_in = g_nin[(size_t)bc * Dd + d];

    float bl = 0.0f, L = -1e30f, Pr = 0.0f;
    for (int g = 0; g < CC; g += 8) {
        float li[8], lf[8], kk[8];
        #pragma unroll
        for (int u = 0; u < 8; u++) {
            size_t idx = base + (size_t)(g + u) * Dd;
            li[u] = g_li[idx]; lf[u] = g_lf[idx]; kk[u] = g_k[idx];
        }
        #pragma unroll
        for (int u = 0; u < 8; u++) {
            size_t idx = base + (size_t)(g + u) * Dd;
            bl += lf[u];
            float e = li[u] - bl;
            L = fmaxf(L, e);
            float mt = bl + fmaxf(m_in, L);
            Pr = fmaf(__expf(e), kk[u], Pr);
            float nt = __expf(bl + m_in - mt) * n_in + __expf(bl - mt) * Pr;
            g_li[idx] = e;
            g_lf[idx] = bl - mt;
            g_n[idx]  = nt;
        }
    }
}

// ---------------------------------------------------------------------------
// prep: U, G, Gamma, sigmoid(o)   (unchanged)
// ---------------------------------------------------------------------------
__global__ __launch_bounds__(256) void prep_kernel()
{
    int i4 = blockIdx.x * 256 + threadIdx.x;
    int d4 = i4 & 63;
    int t  = (i4 >> 6) & 2047;
    int b  = i4 >> 17;
    int c  = t >> 6;

    float4 E  = ((const float4*)g_li)[i4];
    float4 bm = ((const float4*)g_lf)[i4];
    float4 v  = ((const float4*)g_v)[i4];
    float4 op = ((const float4*)g_o)[i4];
    float4 be = ((const float4*)g_bend)[(size_t)(b*NC + c)*64 + d4];
    float4 mp = ((const float4*)g_m)[(size_t)(b*NCH + c)*64 + d4];

    float4 U, G, Ga, sg;
    U.x = __expf(E.x + be.x) * v.x;  U.y = __expf(E.y + be.y) * v.y;
    U.z = __expf(E.z + be.z) * v.z;  U.w = __expf(E.w + be.w) * v.w;
    G.x = __expf(bm.x - be.x); G.y = __expf(bm.y - be.y);
    G.z = __expf(bm.z - be.z); G.w = __expf(bm.w - be.w);
    Ga.x = __expf(bm.x + mp.x); Ga.y = __expf(bm.y + mp.y);
    Ga.z = __expf(bm.z + mp.z); Ga.w = __expf(bm.w + mp.w);
    sg.x = 1.0f/(1.0f + __expf(-op.x)); sg.y = 1.0f/(1.0f + __expf(-op.y));
    sg.z = 1.0f/(1.0f + __expf(-op.z)); sg.w = 1.0f/(1.0f + __expf(-op.w));

    ((float4*)g_v)[i4]  = U;
    ((float4*)g_lf)[i4] = G;
    ((float4*)g_li)[i4] = Ga;
    ((float4*)g_o)[i4]  = sg;
}

// ---------------------------------------------------------------------------
// denom (unchanged)
// ---------------------------------------------------------------------------
__global__ __launch_bounds__(256) void denom_kernel()
{
    const int gw   = blockIdx.x * 8 + (threadIdx.x >> 5);
    const int lane = threadIdx.x & 31;
    size_t base = (size_t)gw * Dd + lane * 8;
    float4 n1 = *(const float4*)&g_n[base];
    float4 n2 = *(const float4*)&g_n[base + 4];
    float4 q1 = *(const float4*)&g_q[base];
    float4 q2 = *(const float4*)&g_q[base + 4];
    float s = n1.x*q1.x + n1.y*q1.y + n1.z*q1.z + n1.w*q1.w
            + n2.x*q2.x + n2.y*q2.y + n2.z*q2.z + n2.w*q2.w;
    #pragma unroll
    for (int o = 16; o; o >>= 1) s += __shfl_xor_sync(0xffffffffu, s, o);
    if (lane == 0) g_den[gw] = fmaxf(fabsf(s), 1e-6f);
}

// ---------------------------------------------------------------------------
// score: per-chunk S[s][t] = k_s . q_t masked (unchanged)
// ---------------------------------------------------------------------------
__global__ __launch_bounds__(256) void score_kernel()
{
    const int b = blockIdx.x >> 5, c = blockIdx.x & 31;
    __shared__ float Qs[64][33];
    __shared__ float Ks[64][33];
    const int tid = threadIdx.x;
    const int sg = tid >> 4, tg = tid & 15;
    float acc[4][4] = {};
    size_t base = ((size_t)b * Tt + c * CC) * Dd;

    for (int db = 0; db < 256; db += 32) {
        __syncthreads();
        for (int l = tid; l < 512; l += 256) {
            int r = l >> 3, q4 = (l & 7) * 4;
            float4 qv = *(const float4*)&g_q[base + (size_t)r*Dd + db + q4];
            float4 kv = *(const float4*)&g_k[base + (size_t)r*Dd + db + q4];
            Qs[r][q4+0]=qv.x; Qs[r][q4+1]=qv.y; Qs[r][q4+2]=qv.z; Qs[r][q4+3]=qv.w;
            Ks[r][q4+0]=kv.x; Ks[r][q4+1]=kv.y; Ks[r][q4+2]=kv.z; Ks[r][q4+3]=kv.w;
        }
        __syncthreads();
        #pragma unroll 8
        for (int dd = 0; dd < 32; dd++) {
            float kv[4], qv[4];
            #pragma unroll
            for (int x = 0; x < 4; x++) { kv[x] = Ks[sg*4+x][dd]; qv[x] = Qs[tg*4+x][dd]; }
            #pragma unroll
            for (int si = 0; si < 4; si++)
                #pragma unroll
                for (int ti = 0; ti < 4; ti++)
                    acc[si][ti] = fmaf(kv[si], qv[ti], acc[si][ti]);
        }
    }

    float* Sp = g_S + (size_t)(b*NC + c) * (CC*CC);
    #pragma unroll
    for (int si = 0; si < 4; si++) {
        int s = sg*4 + si;
        #pragma unroll
        for (int ti = 0; ti < 4; ti++) {
            int t = tg*4 + ti;
            Sp[s*64 + t] = (s <= t) ? acc[si][ti] : 0.0f;
        }
    }
}

// ---------------------------------------------------------------------------
// state_scan: materialize chunk states g_M[b][c][j][i] (pre-update),
//   M <- dec_i * M + esc_i * sum_s K[s][j] U[s][i]
// grid: b(4) x jt(8: 32 j each) x it(4: 64 i each) = 128 CTAs, 256 thr
// thread: tx=tid&15 -> i (float4), ty=tid>>4 -> 2 j rows
// smem (dynamic): Ks[2][64*32], Us[2][64*64], decs[64], escs[64]
// ---------------------------------------------------------------------------
#define SS_K(st)  (2048*(st))
#define SS_U(st)  (4096 + 4096*(st))
#define SS_DEC    12288
#define SS_ESC    12352
#define SS_TOTAL  12416

__global__ __launch_bounds__(256) void state_scan()
{
    extern __shared__ float sm[];
    const int tid = threadIdx.x;
    const int tx = tid & 15, ty = tid >> 4;
    const int blk = blockIdx.x;
    const int b  = blk >> 5;
    const int jt = (blk & 31) >> 2;
    const int it = blk & 3;
    const int j0 = jt * 32, i0 = it * 64;
    const size_t bB = (size_t)b * Tt * Dd;

    auto issue = [&](int c, int st) {
        size_t tb = bB + (size_t)c * CC * Dd;
        #pragma unroll
        for (int h = 0; h < 2; h++) {            // K tile: 512 float4
            int idx = tid + h * 256;
            int row = idx >> 3, f4 = (idx & 7) * 4;
            cpa16(&sm[SS_K(st) + row*32 + f4], g_k + tb + (size_t)row*Dd + j0 + f4);
        }
        #pragma unroll
        for (int h = 0; h < 4; h++) {            // U tile: 1024 float4
            int idx = tid + h * 256;
            int row = idx >> 4, f4 = (idx & 15) * 4;
            cpa16(&sm[SS_U(st) + row*64 + f4], g_v + tb + (size_t)row*Dd + i0 + f4);
        }
    };

    float4 M0 = make_float4(0.f,0.f,0.f,0.f);
    float4 M1 = make_float4(0.f,0.f,0.f,0.f);

    issue(0, 0);
    asm volatile("cp.async.commit_group;");

    for (int c = 0; c < NC; c++) {
        const int st = c & 1;
        if (c + 1 < NC) {
            issue(c + 1, st ^ 1);
            asm volatile("cp.async.commit_group;");
            asm volatile("cp.async.wait_group 1;");
        } else {
            asm volatile("cp.async.wait_group 0;");
        }
        __syncthreads();                        // syncA: tiles ready, prev decs readers done

        if (tid < 64) {
            float be = g_bend[(size_t)(b*NC + c) * Dd + i0 + tid];
            float mp = g_m[(size_t)(b*NCH + c) * Dd + i0 + tid];
            float me = g_m[(size_t)(b*NCH + c + 1) * Dd + i0 + tid];
            sm[SS_DEC + tid] = __expf(be + mp - me);
            sm[SS_ESC + tid] = __expf(-me);
        }

        float4 a0 = make_float4(0.f,0.f,0.f,0.f);
        float4 a1 = make_float4(0.f,0.f,0.f,0.f);
        const float* K_ = &sm[SS_K(st)];
        const float* U_ = &sm[SS_U(st)];
        #pragma unroll 8
        for (int s = 0; s < CC; s++) {
            float2 kv = *(const float2*)&K_[s*32 + ty*2];
            float4 uv = *(const float4*)&U_[s*64 + tx*4];
            a0.x = fmaf(kv.x, uv.x, a0.x); a0.y = fmaf(kv.x, uv.y, a0.y);
            a0.z = fmaf(kv.x, uv.z, a0.z); a0.w = fmaf(kv.x, uv.w, a0.w);
            a1.x = fmaf(kv.y, uv.x, a1.x); a1.y = fmaf(kv.y, uv.y, a1.y);
            a1.z = fmaf(kv.y, uv.z, a1.z); a1.w = fmaf(kv.y, uv.w, a1.w);
        }
        __syncthreads();                        // syncB: compute done; decs ready

        // store pre-update state, then update
        float* gm = g_M + (((size_t)(b*NC + c)) * Dd + (j0 + ty*2)) * Dd + i0 + tx*4;
        *(float4*)&gm[0]   = M0;
        *(float4*)&gm[Dd]  = M1;

        float4 dec = *(const float4*)&sm[SS_DEC + tx*4];
        float4 esc = *(const float4*)&sm[SS_ESC + tx*4];
        M0.x = dec.x*M0.x + esc.x*a0.x;  M0.y = dec.y*M0.y + esc.y*a0.y;
        M0.z = dec.z*M0.z + esc.z*a0.z;  M0.w = dec.w*M0.w + esc.w*a0.w;
        M1.x = dec.x*M1.x + esc.x*a1.x;  M1.y = dec.y*M1.y + esc.y*a1.y;
        M1.z = dec.z*M1.z + esc.z*a1.z;  M1.w = dec.w*M1.w + esc.w*a1.w;
    }
}

// ---------------------------------------------------------------------------
// combine: out = sigma(o) * (Gamma*(Q@M_state) + G*(S^T@U)) / den
// grid: (b*NC)*4 + it  (512 CTAs), 256 thr; tile 64t x 64i
// thread: tx=tid&15 -> i float4, ty=tid>>4 -> 4 t rows
// ---------------------------------------------------------------------------
__global__ __launch_bounds__(256) void combine(float* __restrict__ out)
{
    __shared__ float Qs[64*33];
    __shared__ float Bf[64*64];   // S tile, then M j-blocks
    __shared__ float Uf[64*64];   // U tile

    const int tid = threadIdx.x;
    const int tx = tid & 15, ty = tid >> 4;
    const int blk = blockIdx.x;
    const int it = blk & 3;
    const int bc = blk >> 2;
    const int b = bc >> 5, c = bc & 31;
    const int i0 = it * 64, t0 = c * CC;
    const size_t bB = (size_t)b * Tt * Dd;

    float4 accA[4], accB[4];
    #pragma unroll
    for (int r = 0; r < 4; r++) {
        accA[r] = make_float4(0.f,0.f,0.f,0.f);
        accB[r] = make_float4(0.f,0.f,0.f,0.f);
    }

    // ---- intra: fill S and U tiles ----
    {
        const float* Sg = g_S + (size_t)(b*NC + c) * (CC*CC);
        #pragma unroll
        for (int h = 0; h < 4; h++) {
            int idx = tid + h * 256;
            int row = idx >> 4, f4 = (idx & 15) * 4;
            *(float4*)&Bf[row*64 + f4] = *(const float4*)&Sg[row*64 + f4];
            *(float4*)&Uf[row*64 + f4] =
                *(const float4*)&g_v[bB + (size_t)(t0 + row)*Dd + i0 + f4];
        }
    }
    __syncthreads();
    #pragma unroll 4
    for (int s = 0; s < CC; s++) {
        float4 uv = *(const float4*)&Uf[s*64 + tx*4];
        float s0 = Bf[s*64 + ty*4 + 0];
        float s1 = Bf[s*64 + ty*4 + 1];
        float s2 = Bf[s*64 + ty*4 + 2];
        float s3 = Bf[s*64 + ty*4 + 3];
        accA[0].x = fmaf(s0, uv.x, accA[0].x); accA[0].y = fmaf(s0, uv.y, accA[0].y);
        accA[0].z = fmaf(s0, uv.z, accA[0].z); accA[0].w = fmaf(s0, uv.w, accA[0].w);
        accA[1].x = fmaf(s1, uv.x, accA[1].x); accA[1].y = fmaf(s1, uv.y, accA[1].y);
        accA[1].z = fmaf(s1, uv.z, accA[1].z); accA[1].w = fmaf(s1, uv.w, accA[1].w);
        accA[2].x = fmaf(s2, uv.x, accA[2].x); accA[2].y = fmaf(s2, uv.y, accA[2].y);
        accA[2].z = fmaf(s2, uv.z, accA[2].z); accA[2].w = fmaf(s2, uv.w, accA[2].w);
        accA[3].x = fmaf(s3, uv.x, accA[3].x); accA[3].y = fmaf(s3, uv.y, accA[3].y);
        accA[3].z = fmaf(s3, uv.z, accA[3].z); accA[3].w = fmaf(s3, uv.w, accA[3].w);
    }

    // ---- inter: 8 j-blocks of Q@M ----
    const float* Mg = g_M + ((size_t)(b*NC + c)) * Dd * Dd;
    for (int jb = 0; jb < 8; jb++) {
        __syncthreads();
        #pragma unroll
        for (int h = 0; h < 2; h++) {          // Q block: 64 x 32
            int idx = tid + h * 256;
            int row = idx >> 3, f4 = (idx & 7) * 4;
            float4 qv = *(const float4*)&g_q[bB + (size_t)(t0 + row)*Dd + jb*32 + f4];
            Qs[row*33 + f4+0] = qv.x; Qs[row*33 + f4+1] = qv.y;
            Qs[row*33 + f4+2] = qv.z; Qs[row*33 + f4+3] = qv.w;
        }
        #pragma unroll
        for (int h = 0; h < 2; h++) {          // M block: 32 x 64
            int idx = tid + h * 256;
            int row = idx >> 4, f4 = (idx & 15) * 4;
            *(float4*)&Bf[row*64 + f4] =
                *(const float4*)&Mg[(size_t)(jb*32 + row)*Dd + i0 + f4];
        }
        __syncthreads();
        #pragma unroll 4
        for (int j = 0; j < 32; j++) {
            float4 mv = *(const float4*)&Bf[j*64 + tx*4];
            float q0 = Qs[(ty*4 + 0)*33 + j];
            float q1 = Qs[(ty*4 + 1)*33 + j];
            float q2 = Qs[(ty*4 + 2)*33 + j];
            float q3 = Qs[(ty*4 + 3)*33 + j];
            accB[0].x = fmaf(q0, mv.x, accB[0].x); accB[0].y = fmaf(q0, mv.y, accB[0].y);
            accB[0].z = fmaf(q0, mv.z, accB[0].z); accB[0].w = fmaf(q0, mv.w, accB[0].w);
            accB[1].x = fmaf(q1, mv.x, accB[1].x); accB[1].y = fmaf(q1, mv.y, accB[1].y);
            accB[1].z = fmaf(q1, mv.z, accB[1].z); accB[1].w = fmaf(q1, mv.w, accB[1].w);
            accB[2].x = fmaf(q2, mv.x, accB[2].x); accB[2].y = fmaf(q2, mv.y, accB[2].y);
            accB[2].z = fmaf(q2, mv.z, accB[2].z); accB[2].w = fmaf(q2, mv.w, accB[2].w);
            accB[3].x = fmaf(q3, mv.x, accB[3].x); accB[3].y = fmaf(q3, mv.y, accB[3].y);
            accB[3].z = fmaf(q3, mv.z, accB[3].z); accB[3].w = fmaf(q3, mv.w, accB[3].w);
        }
    }

    // ---- epilogue ----
    #pragma unroll
    for (int r = 0; r < 4; r++) {
        int t = ty*4 + r;
        size_t gb = bB + (size_t)(t0 + t)*Dd + i0 + tx*4;
        float4 Ga = *(const float4*)&g_li[gb];
        float4 Gg = *(const float4*)&g_lf[gb];
        float4 sg = *(const float4*)&g_o[gb];
        float rd = 1.0f / g_den[(size_t)b*Tt + t0 + t];
        float4 o;
        o.x = sg.x * (Ga.x*accB[r].x + Gg.x*accA[r].x) * rd;
        o.y = sg.y * (Ga.y*accB[r].y + Gg.y*accA[r].y) * rd;
        o.z = sg.z * (Ga.z*accB[r].z + Gg.z*accA[r].z) * rd;
        o.w = sg.w * (Ga.w*accB[r].w + Gg.w*accA[r].w) * rd;
        *(float4*)&out[gb] = o;
    }
}

// ---------------------------------------------------------------------------
// RMSNorm in place
// ---------------------------------------------------------------------------
__global__ __launch_bounds__(256) void rmsnorm_kernel(float* __restrict__ out,
                                                      const float* __restrict__ ns)
{
    const int gw   = blockIdx.x * 8 + (threadIdx.x >> 5);
    const int lane = threadIdx.x & 31;
    size_t base = (size_t)gw * Dd + lane * 8;
    float4 a = *(const float4*)&out[base];
    float4 c = *(const float4*)&out[base + 4];
    float ss = a.x*a.x + a.y*a.y + a.z*a.z + a.w*a.w
             + c.x*c.x + c.y*c.y + c.z*c.z + c.w*c.w;
    #pragma unroll
    for (int o = 16; o; o >>= 1) ss += __shfl_xor_sync(0xffffffffu, ss, o);
    float rinv = rsqrtf(ss * (1.0f / Dd) + 1e-8f);
    float4 s1 = *(const float4*)&ns[lane * 8];
    float4 s2 = *(const float4*)&ns[lane * 8 + 4];
    a.x *= rinv * s1.x; a.y *= rinv * s1.y; a.z *= rinv * s1.z; a.w *= rinv * s1.w;
    c.x *= rinv * s2.x; c.y *= rinv * s2.y; c.z *= rinv * s2.z; c.w *= rinv * s2.w;
    *(float4*)&out[base]     = a;
    *(float4*)&out[base + 4] = c;
}

// ---------------------------------------------------------------------------
extern "C" void kernel_launch(void* const* d_in, const int* in_sizes, int n_in,
                              void* d_out, int out_size)
{
    const float* x  = (const float*)d_in[0];
    const float* Wq = (const float*)d_in[1];
    const float* bq = (const float*)d_in[2];
    const float* Wk = (const float*)d_in[3];
    const float* bk = (const float*)d_in[4];
    const float* Wv = (const float*)d_in[5];
    const float* bv = (const float*)d_in[6];
    const float* Wg = (const float*)d_in[7];
    const float* bg = (const float*)d_in[8];
    const float* ib = (const float*)d_in[9];
    const float* ns = (const float*)d_in[10];
    float* out = (float*)d_out;

    cudaFuncSetAttribute(state_scan, cudaFuncAttributeMaxDynamicSharedMemorySize,
                         SS_TOTAL * 4);

    dim3 ggrid(24, 64);
    proj_gemm<<<ggrid, 256>>>(x, Wq, bq, Wk, bk, Wv, bv, Wg, bg, ib);
    chanA<<<128, 256>>>();
    chanB<<<4, 256>>>();
    chanC<<<128, 256>>>();
    score_kernel<<<128, 256>>>();
    prep_kernel<<<BTD/4/256, 256>>>();
    denom_kernel<<<1024, 256>>>();
    state_scan<<<128, 256, SS_TOTAL * 4>>>();
    combine<<<512, 256>>>(out);
    rmsnorm_kernel<<<1024, 256>>>(out, ns);
}

// round 8
// speedup vs baseline: 6.0700x; 1.1747x over previous
#include <cuda_runtime.h>
#include <math.h>

#define Bb 4
#define Tt 2048
#define Dd 256
#define BT (Bb*Tt)
#define BTD (Bb*Tt*Dd)
#define CC 64
#define NC 32
#define NCH 33

// Scratch (static __device__ — no allocations allowed)
__device__ float g_q[BTD];
__device__ float g_k[BTD];            // scaled by 1/sqrt(D)
__device__ float g_v[BTD];            // -> U after chanC
__device__ float g_li[BTD];           // log_i -> Gamma (chanC)
__device__ float g_lf[BTD];           // log_f -> G     (chanC)
__device__ float g_o[BTD];            // o_pre -> sigmoid(o) (chanC)
__device__ float g_n[BTD];
__device__ float g_den[BT];           // RECIPROCAL of denom
__device__ float g_S[Bb*NC*CC*CC];    // masked scores, TRANSPOSED: St[t][s]
__device__ float g_m[Bb*NCH*Dd];      // m at chunk starts + final
__device__ float g_bend[Bb*NC*Dd];    // B (sum lf within chunk)
__device__ float g_L[Bb*NC*Dd];       // local max(li - b_t)
__device__ float g_P[Bb*NC*Dd];       // local sum exp(li - b_t) k
__device__ float g_nin[Bb*NC*Dd];     // n at chunk start
__device__ float g_M[(size_t)Bb*NC*Dd*Dd];  // chunk states [b][c][j][i]

// ---------------------------------------------------------------------------
// bf16x3 helpers: f = hi + lo with 16-bit effective mantissa
// ---------------------------------------------------------------------------
__device__ __forceinline__ void split3(float f0, float f1, unsigned &hi, unsigned &lo)
{
    unsigned h;
    asm("cvt.rn.bf16x2.f32 %0, %1, %2;" : "=r"(h) : "f"(f1), "f"(f0));
    float h0 = __uint_as_float(h << 16);
    float h1 = __uint_as_float(h & 0xFFFF0000u);
    unsigned l;
    asm("cvt.rn.bf16x2.f32 %0, %1, %2;" : "=r"(l) : "f"(f1 - h1), "f"(f0 - h0));
    hi = h; lo = l;
}
__device__ __forceinline__ void mma_bf16(float* d, const unsigned* a, const unsigned* b)
{
    asm volatile(
        "mma.sync.aligned.m16n8k16.row.col.f32.bf16.bf16.f32 "
        "{%0,%1,%2,%3}, {%4,%5,%6,%7}, {%8,%9}, {%0,%1,%2,%3};"
        : "+f"(d[0]), "+f"(d[1]), "+f"(d[2]), "+f"(d[3])
        : "r"(a[0]), "r"(a[1]), "r"(a[2]), "r"(a[3]),
          "r"(b[0]), "r"(b[1]));
}
__device__ __forceinline__ void cpa16(void* sm, const void* g) {
    unsigned s = (unsigned)__cvta_generic_to_shared(sm);
    asm volatile("cp.async.ca.shared.global [%0], [%1], 16;" :: "r"(s), "l"(g));
}

// ---------------------------------------------------------------------------
// Kernel 1: projection GEMM (8192 x 1536 x 256) via 3xBF16 m16n8k16
// CTA tile 128x64, 8 warps of 32x32, k-tile 16, double-buffered cp.async.
// ---------------------------------------------------------------------------
#define AS_STRIDE 20
#define BS_STRIDE 72

__global__ __launch_bounds__(256, 2) void proj_gemm(
    const float* __restrict__ x,
    const float* __restrict__ Wq, const float* __restrict__ bq,
    const float* __restrict__ Wk, const float* __restrict__ bk,
    const float* __restrict__ Wv, const float* __restrict__ bv,
    const float* __restrict__ Wg, const float* __restrict__ bg,
    const float* __restrict__ ib)
{
    __shared__ float As[2][128 * AS_STRIDE];
    __shared__ float Bs[2][16 * BS_STRIDE];

    const int tid  = threadIdx.x;
    const int warp = tid >> 5, lane = tid & 31;
    const int g    = lane >> 2, q = lane & 3;
    const int wm   = (warp >> 1) * 32;
    const int wn   = (warp & 1) * 32;

    const int mBase = blockIdx.y * 128;
    const int nBase = blockIdx.x * 64;

    const float* W;  const float* bias;  float* outArr;
    int ldw, colW, outCol, mode;
    if (nBase < 256)      { W = Wq; ldw = 256; colW = nBase;       bias = bq; outArr = g_q;  mode = 0; }
    else if (nBase < 512) { W = Wk; ldw = 256; colW = nBase - 256; bias = bk; outArr = g_k;  mode = 1; }
    else if (nBase < 768) { W = Wv; ldw = 256; colW = nBase - 512; bias = bv; outArr = g_v;  mode = 0; }
    else {
        W = Wg; ldw = 768; colW = nBase - 768; bias = bg;
        int gi = colW >> 8;
        outArr = (gi == 0) ? g_li : ((gi == 1) ? g_lf : g_o);
        mode   = (gi == 0) ? 2 : ((gi == 1) ? 3 : 0);
    }
    outCol = (nBase < 768) ? colW : (colW & 255);

    auto issue = [&](int kt, int st) {
        const int c0 = kt * 16;
        #pragma unroll
        for (int h = 0; h < 2; h++) {
            int idx = tid + h * 256;
            int r = idx >> 2, cc = (idx & 3) << 2;
            cpa16(&As[st][r * AS_STRIDE + cc],
                  x + (size_t)(mBase + r) * 256 + c0 + cc);
        }
        {
            int k = tid >> 4, n4 = (tid & 15) << 2;
            cpa16(&Bs[st][k * BS_STRIDE + n4],
                  W + (size_t)(c0 + k) * ldw + colW + n4);
        }
    };

    float acc[2][4][4];
    #pragma unroll
    for (int mf = 0; mf < 2; mf++)
        #pragma unroll
        for (int nf = 0; nf < 4; nf++)
            #pragma unroll
            for (int r = 0; r < 4; r++) acc[mf][nf][r] = 0.0f;

    issue(0, 0);
    asm volatile("cp.async.commit_group;");

    for (int kt = 0; kt < 16; kt++) {
        const int st = kt & 1;
        if (kt < 15) {
            issue(kt + 1, st ^ 1);
            asm volatile("cp.async.commit_group;");
            asm volatile("cp.async.wait_group 1;");
        } else {
            asm volatile("cp.async.wait_group 0;");
        }
        __syncthreads();

        const float* A_ = As[st];
        const float* B_ = Bs[st];

        unsigned ah[2][4], al[2][4];
        #pragma unroll
        for (int mf = 0; mf < 2; mf++) {
            int r0 = wm + mf * 16 + g;
            float2 p00 = *(const float2*)&A_[r0 * AS_STRIDE + 2*q];
            float2 p10 = *(const float2*)&A_[(r0 + 8) * AS_STRIDE + 2*q];
            float2 p01 = *(const float2*)&A_[r0 * AS_STRIDE + 2*q + 8];
            float2 p11 = *(const float2*)&A_[(r0 + 8) * AS_STRIDE + 2*q + 8];
            split3(p00.x, p00.y, ah[mf][0], al[mf][0]);
            split3(p10.x, p10.y, ah[mf][1], al[mf][1]);
            split3(p01.x, p01.y, ah[mf][2], al[mf][2]);
            split3(p11.x, p11.y, ah[mf][3], al[mf][3]);
        }
        unsigned bh[4][2], bl[4][2];
        #pragma unroll
        for (int nf = 0; nf < 4; nf++) {
            int cN = wn + nf * 8 + g;
            float f0 = B_[(2*q)     * BS_STRIDE + cN];
            float f1 = B_[(2*q + 1) * BS_STRIDE + cN];
            float f2 = B_[(2*q + 8) * BS_STRIDE + cN];
            float f3 = B_[(2*q + 9) * BS_STRIDE + cN];
            split3(f0, f1, bh[nf][0], bl[nf][0]);
            split3(f2, f3, bh[nf][1], bl[nf][1]);
        }
        #pragma unroll
        for (int mf = 0; mf < 2; mf++)
            #pragma unroll
            for (int nf = 0; nf < 4; nf++) {
                mma_bf16(acc[mf][nf], ah[mf], bh[nf]);
                mma_bf16(acc[mf][nf], ah[mf], bl[nf]);
                mma_bf16(acc[mf][nf], al[mf], bh[nf]);
            }
        __syncthreads();
    }

    #pragma unroll
    for (int mf = 0; mf < 2; mf++) {
        int row0 = mBase + wm + mf * 16 + g;
        #pragma unroll
        for (int nf = 0; nf < 4; nf++) {
            int nl = wn + nf * 8 + 2 * q;
            float vals[4] = { acc[mf][nf][0], acc[mf][nf][1],
                              acc[mf][nf][2], acc[mf][nf][3] };
            #pragma unroll
            for (int e = 0; e < 4; e++) {
                int cl = nl + (e & 1);
                float val = vals[e] + bias[colW + cl];
                if (mode == 1) {
                    val *= 0.0625f;
                } else if (mode == 2) {
                    val += ib[outCol + cl];
                    val = 10.0f * tanhf(val * 0.1f);
                } else if (mode == 3) {
                    val = -(fmaxf(val, 0.0f) + log1pf(__expf(-fabsf(val))));
                }
                vals[e] = val;
            }
            int row1 = row0 + 8;
            *(float2*)&outArr[(size_t)row0 * 256 + outCol + nl] = make_float2(vals[0], vals[1]);
            *(float2*)&outArr[(size_t)row1 * 256 + outCol + nl] = make_float2(vals[2], vals[3]);
        }
    }
}

// ---------------------------------------------------------------------------
// chan phase A: per (b,c,d) local chunk reductions: B=sum lf, L=max(li-b), P
// ---------------------------------------------------------------------------
__global__ __launch_bounds__(256) void chanA()
{
    const int bc = blockIdx.x;             // b*NC + c
    const int d  = threadIdx.x;
    const int b  = bc >> 5, c = bc & 31;
    size_t base = (size_t)b * Tt * Dd + (size_t)c * CC * Dd + d;

    float bl = 0.0f, L = -1e30f, P = 0.0f;
    for (int g = 0; g < CC; g += 8) {
        float li[8], lf[8], kk[8];
        #pragma unroll
        for (int u = 0; u < 8; u++) {
            size_t idx = base + (size_t)(g + u) * Dd;
            li[u] = g_li[idx]; lf[u] = g_lf[idx]; kk[u] = g_k[idx];
        }
        #pragma unroll
        for (int u = 0; u < 8; u++) {
            bl += lf[u];
            float e = li[u] - bl;
            L = fmaxf(L, e);
            P = fmaf(__expf(e), kk[u], P);
        }
    }
    g_bend[(size_t)bc * Dd + d] = bl;
    g_L[(size_t)bc * Dd + d]    = L;
    g_P[(size_t)bc * Dd + d]    = P;
}

// ---------------------------------------------------------------------------
// chan phase B: sequential stitch over 32 chunks
// ---------------------------------------------------------------------------
__global__ __launch_bounds__(256) void chanB()
{
    const int b = blockIdx.x, d = threadIdx.x;
    float m = 0.0f, n = 0.0f;
    for (int c = 0; c < NC; c++) {
        g_m[(size_t)(b*NCH + c) * Dd + d]  = m;
        g_nin[(size_t)(b*NC + c) * Dd + d] = n;
        float B = g_bend[(size_t)(b*NC + c) * Dd + d];
        float L = g_L[(size_t)(b*NC + c) * Dd + d];
        float P = g_P[(size_t)(b*NC + c) * Dd + d];
        float me = B + fmaxf(m, L);
        n = __expf(B + m - me) * n + __expf(B - me) * P;
        m = me;
    }
    g_m[(size_t)(b*NCH + NC) * Dd + d] = m;
}

// ---------------------------------------------------------------------------
// chan phase C (fused with prep): writes n, U, G, Gamma, sigmoid(o)
// ---------------------------------------------------------------------------
__global__ __launch_bounds__(256) void chanC()
{
    const int bc = blockIdx.x;
    const int d  = threadIdx.x;
    const int b  = bc >> 5, c = bc & 31;
    size_t base = (size_t)b * Tt * Dd + (size_t)c * CC * Dd + d;

    const float be   = g_bend[(size_t)bc * Dd + d];
    const float m_in = g_m[(size_t)(b*NCH + c) * Dd + d];
    const float n_in = g_nin[(size_t)bc * Dd + d];

    float bl = 0.0f, L = -1e30f, Pr = 0.0f;
    for (int g = 0; g < CC; g += 8) {
        float li[8], lf[8], kk[8], vv[8], oo[8];
        #pragma unroll
        for (int u = 0; u < 8; u++) {
            size_t idx = base + (size_t)(g + u) * Dd;
            li[u] = g_li[idx]; lf[u] = g_lf[idx]; kk[u] = g_k[idx];
            vv[u] = g_v[idx];  oo[u] = g_o[idx];
        }
        #pragma unroll
        for (int u = 0; u < 8; u++) {
            size_t idx = base + (size_t)(g + u) * Dd;
            bl += lf[u];
            float e = li[u] - bl;
            L = fmaxf(L, e);
            float mt = bl + fmaxf(m_in, L);
            Pr = fmaf(__expf(e), kk[u], Pr);
            float nt = __expf(bl + m_in - mt) * n_in + __expf(bl - mt) * Pr;
            float bm = bl - mt;
            g_n[idx]  = nt;
            g_v[idx]  = __expf(e + be) * vv[u];          // U
            g_lf[idx] = __expf(bm - be);                 // G
            g_li[idx] = __expf(bm + m_in);               // Gamma
            g_o[idx]  = 1.0f / (1.0f + __expf(-oo[u]));  // sigmoid
        }
    }
}

// ---------------------------------------------------------------------------
// denom: g_den[b,t] = 1 / max(|n_t . q_t|, 1e-6)   (reciprocal!)
// ---------------------------------------------------------------------------
__global__ __launch_bounds__(256) void denom_kernel()
{
    const int gw   = blockIdx.x * 8 + (threadIdx.x >> 5);
    const int lane = threadIdx.x & 31;
    size_t base = (size_t)gw * Dd + lane * 8;
    float4 n1 = *(const float4*)&g_n[base];
    float4 n2 = *(const float4*)&g_n[base + 4];
    float4 q1 = *(const float4*)&g_q[base];
    float4 q2 = *(const float4*)&g_q[base + 4];
    float s = n1.x*q1.x + n1.y*q1.y + n1.z*q1.z + n1.w*q1.w
            + n2.x*q2.x + n2.y*q2.y + n2.z*q2.z + n2.w*q2.w;
    #pragma unroll
    for (int o = 16; o; o >>= 1) s += __shfl_xor_sync(0xffffffffu, s, o);
    if (lane == 0) g_den[gw] = 1.0f / fmaxf(fabsf(s), 1e-6f);
}

// ---------------------------------------------------------------------------
// score: per-chunk St[t][s] = k_s . q_t, masked (s<=t), via 3xBF16 mma
// CTA = (b,c); 8 warps: 2(s) x 4(t); warp tile 32s x 16t
// ---------------------------------------------------------------------------
__global__ __launch_bounds__(256) void score_kernel()
{
    const int b = blockIdx.x >> 5, c = blockIdx.x & 31;
    __shared__ float Ks[64 * 36];
    __shared__ float Qs[64 * 36];
    const int tid  = threadIdx.x;
    const int warp = tid >> 5, lane = tid & 31;
    const int g    = lane >> 2, q = lane & 3;
    const int wm   = (warp >> 2) * 32;   // s base
    const int wn   = (warp & 3) * 16;    // t base
    size_t base = ((size_t)b * Tt + c * CC) * Dd;

    float acc[2][2][4];
    #pragma unroll
    for (int mf = 0; mf < 2; mf++)
        #pragma unroll
        for (int nf = 0; nf < 2; nf++)
            #pragma unroll
            for (int r = 0; r < 4; r++) acc[mf][nf][r] = 0.0f;

    for (int db = 0; db < 256; db += 32) {
        __syncthreads();
        #pragma unroll
        for (int h = 0; h < 2; h++) {
            int idx = tid + h * 256;
            int r = idx >> 3, c4 = (idx & 7) * 4;
            *(float4*)&Ks[r*36 + c4] = *(const float4*)&g_k[base + (size_t)r*Dd + db + c4];
            *(float4*)&Qs[r*36 + c4] = *(const float4*)&g_q[base + (size_t)r*Dd + db + c4];
        }
        __syncthreads();
        #pragma unroll
        for (int ks = 0; ks < 32; ks += 16) {
            unsigned ah[2][4], al[2][4], bh[2][2], bl[2][2];
            #pragma unroll
            for (int mf = 0; mf < 2; mf++) {
                int r0 = wm + mf * 16 + g;
                float2 p00 = *(const float2*)&Ks[r0*36 + ks + 2*q];
                float2 p10 = *(const float2*)&Ks[(r0+8)*36 + ks + 2*q];
                float2 p01 = *(const float2*)&Ks[r0*36 + ks + 2*q + 8];
                float2 p11 = *(const float2*)&Ks[(r0+8)*36 + ks + 2*q + 8];
                split3(p00.x, p00.y, ah[mf][0], al[mf][0]);
                split3(p10.x, p10.y, ah[mf][1], al[mf][1]);
                split3(p01.x, p01.y, ah[mf][2], al[mf][2]);
                split3(p11.x, p11.y, ah[mf][3], al[mf][3]);
            }
            #pragma unroll
            for (int nf = 0; nf < 2; nf++) {
                int t = wn + nf * 8 + g;
                float2 u0 = *(const float2*)&Qs[t*36 + ks + 2*q];
                float2 u1 = *(const float2*)&Qs[t*36 + ks + 2*q + 8];
                split3(u0.x, u0.y, bh[nf][0], bl[nf][0]);
                split3(u1.x, u1.y, bh[nf][1], bl[nf][1]);
            }
            #pragma unroll
            for (int mf = 0; mf < 2; mf++)
                #pragma unroll
                for (int nf = 0; nf < 2; nf++) {
                    mma_bf16(acc[mf][nf], ah[mf], bh[nf]);
                    mma_bf16(acc[mf][nf], ah[mf], bl[nf]);
                    mma_bf16(acc[mf][nf], al[mf], bh[nf]);
                }
        }
    }

    float* Sp = g_S + (size_t)(b*NC + c) * (CC*CC);
    #pragma unroll
    for (int mf = 0; mf < 2; mf++) {
        int s0 = wm + mf * 16 + g;
        #pragma unroll
        for (int nf = 0; nf < 2; nf++) {
            int t0_ = wn + nf * 8 + 2 * q;
            const float* a = acc[mf][nf];
            Sp[(t0_    )*64 + s0    ] = (s0     <= t0_    ) ? a[0] : 0.0f;
            Sp[(t0_ + 1)*64 + s0    ] = (s0     <= t0_ + 1) ? a[1] : 0.0f;
            Sp[(t0_    )*64 + s0 + 8] = (s0 + 8 <= t0_    ) ? a[2] : 0.0f;
            Sp[(t0_ + 1)*64 + s0 + 8] = (s0 + 8 <= t0_ + 1) ? a[3] : 0.0f;
        }
    }
}

// ---------------------------------------------------------------------------
// state_scan: materialize chunk states (unchanged SIMT)
// ---------------------------------------------------------------------------
#define SS_K(st)  (2048*(st))
#define SS_U(st)  (4096 + 4096*(st))
#define SS_DEC    12288
#define SS_ESC    12352
#define SS_TOTAL  12416

__global__ __launch_bounds__(256) void state_scan()
{
    extern __shared__ float sm[];
    const int tid = threadIdx.x;
    const int tx = tid & 15, ty = tid >> 4;
    const int blk = blockIdx.x;
    const int b  = blk >> 5;
    const int jt = (blk & 31) >> 2;
    const int it = blk & 3;
    const int j0 = jt * 32, i0 = it * 64;
    const size_t bB = (size_t)b * Tt * Dd;

    auto issue = [&](int c, int st) {
        size_t tb = bB + (size_t)c * CC * Dd;
        #pragma unroll
        for (int h = 0; h < 2; h++) {
            int idx = tid + h * 256;
            int row = idx >> 3, f4 = (idx & 7) * 4;
            cpa16(&sm[SS_K(st) + row*32 + f4], g_k + tb + (size_t)row*Dd + j0 + f4);
        }
        #pragma unroll
        for (int h = 0; h < 4; h++) {
            int idx = tid + h * 256;
            int row = idx >> 4, f4 = (idx & 15) * 4;
            cpa16(&sm[SS_U(st) + row*64 + f4], g_v + tb + (size_t)row*Dd + i0 + f4);
        }
    };

    float4 M0 = make_float4(0.f,0.f,0.f,0.f);
    float4 M1 = make_float4(0.f,0.f,0.f,0.f);

    issue(0, 0);
    asm volatile("cp.async.commit_group;");

    for (int c = 0; c < NC; c++) {
        const int st = c & 1;
        if (c + 1 < NC) {
            issue(c + 1, st ^ 1);
            asm volatile("cp.async.commit_group;");
            asm volatile("cp.async.wait_group 1;");
        } else {
            asm volatile("cp.async.wait_group 0;");
        }
        __syncthreads();

        if (tid < 64) {
            float be = g_bend[(size_t)(b*NC + c) * Dd + i0 + tid];
            float mp = g_m[(size_t)(b*NCH + c) * Dd + i0 + tid];
            float me = g_m[(size_t)(b*NCH + c + 1) * Dd + i0 + tid];
            sm[SS_DEC + tid] = __expf(be + mp - me);
            sm[SS_ESC + tid] = __expf(-me);
        }

        float4 a0 = make_float4(0.f,0.f,0.f,0.f);
        float4 a1 = make_float4(0.f,0.f,0.f,0.f);
        const float* K_ = &sm[SS_K(st)];
        const float* U_ = &sm[SS_U(st)];
        #pragma unroll 8
        for (int s = 0; s < CC; s++) {
            float2 kv = *(const float2*)&K_[s*32 + ty*2];
            float4 uv = *(const float4*)&U_[s*64 + tx*4];
            a0.x = fmaf(kv.x, uv.x, a0.x); a0.y = fmaf(kv.x, uv.y, a0.y);
            a0.z = fmaf(kv.x, uv.z, a0.z); a0.w = fmaf(kv.x, uv.w, a0.w);
            a1.x = fmaf(kv.y, uv.x, a1.x); a1.y = fmaf(kv.y, uv.y, a1.y);
            a1.z = fmaf(kv.y, uv.z, a1.z); a1.w = fmaf(kv.y, uv.w, a1.w);
        }
        __syncthreads();

        float* gm = g_M + (((size_t)(b*NC + c)) * Dd + (j0 + ty*2)) * Dd + i0 + tx*4;
        *(float4*)&gm[0]   = M0;
        *(float4*)&gm[Dd]  = M1;

        float4 dec = *(const float4*)&sm[SS_DEC + tx*4];
        float4 esc = *(const float4*)&sm[SS_ESC + tx*4];
        M0.x = dec.x*M0.x + esc.x*a0.x;  M0.y = dec.y*M0.y + esc.y*a0.y;
        M0.z = dec.z*M0.z + esc.z*a0.z;  M0.w = dec.w*M0.w + esc.w*a0.w;
        M1.x = dec.x*M1.x + esc.x*a1.x;  M1.y = dec.y*M1.y + esc.y*a1.y;
        M1.z = dec.z*M1.z + esc.z*a1.z;  M1.w = dec.w*M1.w + esc.w*a1.w;
    }
}

// ---------------------------------------------------------------------------
// combine: out = sig(o)*(Gamma*(Q@M) + G*(St@U)) * rden  via 3xBF16 mma
// grid: 512 CTAs = (b*NC + c)*4 + it. 8 warps: 2(t) x 4(i); warp 32t x 16i
// ---------------------------------------------------------------------------
#define CB_R1 0
#define CB_R2 4352
#define CB_TOT 8704

__global__ __launch_bounds__(256) void combine(float* __restrict__ out)
{
    __shared__ float sm[CB_TOT];
    const int tid  = threadIdx.x;
    const int warp = tid >> 5, lane = tid & 31;
    const int g    = lane >> 2, q = lane & 3;
    const int wm   = (warp >> 2) * 32;   // t base
    const int wn   = (warp & 3) * 16;    // i base
    const int blk = blockIdx.x;
    const int it = blk & 3;
    const int bc = blk >> 2;
    const int b = bc >> 5, c = bc & 31;
    const int i0 = it * 64, t0 = c * CC;
    const size_t bB = (size_t)b * Tt * Dd;

    float accA[2][2][4], accB[2][2][4];
    #pragma unroll
    for (int mf = 0; mf < 2; mf++)
        #pragma unroll
        for (int nf = 0; nf < 2; nf++)
            #pragma unroll
            for (int r = 0; r < 4; r++) { accA[mf][nf][r] = 0.0f; accB[mf][nf][r] = 0.0f; }

    // fill St (R2) and U (R1)
    {
        const float* Sg = g_S + (size_t)bc * (CC*CC);
        #pragma unroll
        for (int h = 0; h < 4; h++) {
            int idx = tid + h * 256;
            int r = idx >> 4, c4 = (idx & 15) * 4;
            *(float4*)&sm[CB_R2 + r*68 + c4] = *(const float4*)&Sg[r*64 + c4];
            *(float4*)&sm[CB_R1 + r*68 + c4] =
                *(const float4*)&g_v[bB + (size_t)(t0 + r)*Dd + i0 + c4];
        }
    }
    __syncthreads();

    // intra: A = St[t][s] (R2, stride 68), B = U[s][i] (R1, stride 68)
    #pragma unroll
    for (int ks = 0; ks < 64; ks += 16) {
        unsigned ah[2][4], al[2][4], bh[2][2], bl[2][2];
        #pragma unroll
        for (int mf = 0; mf < 2; mf++) {
            int r0 = wm + mf * 16 + g;
            float2 p00 = *(const float2*)&sm[CB_R2 + r0*68 + ks + 2*q];
            float2 p10 = *(const float2*)&sm[CB_R2 + (r0+8)*68 + ks + 2*q];
            float2 p01 = *(const float2*)&sm[CB_R2 + r0*68 + ks + 2*q + 8];
            float2 p11 = *(const float2*)&sm[CB_R2 + (r0+8)*68 + ks + 2*q + 8];
            split3(p00.x, p00.y, ah[mf][0], al[mf][0]);
            split3(p10.x, p10.y, ah[mf][1], al[mf][1]);
            split3(p01.x, p01.y, ah[mf][2], al[mf][2]);
            split3(p11.x, p11.y, ah[mf][3], al[mf][3]);
        }
        #pragma unroll
        for (int nf = 0; nf < 2; nf++) {
            int i = wn + nf * 8 + g;
            float f0 = sm[CB_R1 + (ks + 2*q    )*68 + i];
            float f1 = sm[CB_R1 + (ks + 2*q + 1)*68 + i];
            float f2 = sm[CB_R1 + (ks + 2*q + 8)*68 + i];
            float f3 = sm[CB_R1 + (ks + 2*q + 9)*68 + i];
            split3(f0, f1, bh[nf][0], bl[nf][0]);
            split3(f2, f3, bh[nf][1], bl[nf][1]);
        }
        #pragma unroll
        for (int mf = 0; mf < 2; mf++)
            #pragma unroll
            for (int nf = 0; nf < 2; nf++) {
                mma_bf16(accA[mf][nf], ah[mf], bh[nf]);
                mma_bf16(accA[mf][nf], ah[mf], bl[nf]);
                mma_bf16(accA[mf][nf], al[mf], bh[nf]);
            }
    }

    // inter: 8 j-blocks of Q@M.  Q -> R1 [64][36], M -> R2 [32][68]
    const float* Mg = g_M + (size_t)bc * Dd * Dd;
    for (int jb = 0; jb < 8; jb++) {
        __syncthreads();
        #pragma unroll
        for (int h = 0; h < 2; h++) {
            int idx = tid + h * 256;
            int r = idx >> 3, c4 = (idx & 7) * 4;
            *(float4*)&sm[CB_R1 + r*36 + c4] =
                *(const float4*)&g_q[bB + (size_t)(t0 + r)*Dd + jb*32 + c4];
        }
        #pragma unroll
        for (int h = 0; h < 2; h++) {
            int idx = tid + h * 256;
            int r = idx >> 4, c4 = (idx & 15) * 4;
            *(float4*)&sm[CB_R2 + r*68 + c4] =
                *(const float4*)&Mg[(size_t)(jb*32 + r)*Dd + i0 + c4];
        }
        __syncthreads();
        #pragma unroll
        for (int ks = 0; ks < 32; ks += 16) {
            unsigned ah[2][4], al[2][4], bh[2][2], bl[2][2];
            #pragma unroll
            for (int mf = 0; mf < 2; mf++) {
                int r0 = wm + mf * 16 + g;
                float2 p00 = *(const float2*)&sm[CB_R1 + r0*36 + ks + 2*q];
                float2 p10 = *(const float2*)&sm[CB_R1 + (r0+8)*36 + ks + 2*q];
                float2 p01 = *(const float2*)&sm[CB_R1 + r0*36 + ks + 2*q + 8];
                float2 p11 = *(const float2*)&sm[CB_R1 + (r0+8)*36 + ks + 2*q + 8];
                split3(p00.x, p00.y, ah[mf][0], al[mf][0]);
                split3(p10.x, p10.y, ah[mf][1], al[mf][1]);
                split3(p01.x, p01.y, ah[mf][2], al[mf][2]);
                split3(p11.x, p11.y, ah[mf][3], al[mf][3]);
            }
            #pragma unroll
            for (int nf = 0; nf < 2; nf++) {
                int i = wn + nf * 8 + g;
                float f0 = sm[CB_R2 + (ks + 2*q    )*68 + i];
                float f1 = sm[CB_R2 + (ks + 2*q + 1)*68 + i];
                float f2 = sm[CB_R2 + (ks + 2*q + 8)*68 + i];
                float f3 = sm[CB_R2 + (ks + 2*q + 9)*68 + i];
                split3(f0, f1, bh[nf][0], bl[nf][0]);
                split3(f2, f3, bh[nf][1], bl[nf][1]);
            }
            #pragma unroll
            for (int mf = 0; mf < 2; mf++)
                #pragma unroll
                for (int nf = 0; nf < 2; nf++) {
                    mma_bf16(accB[mf][nf], ah[mf], bh[nf]);
                    mma_bf16(accB[mf][nf], ah[mf], bl[nf]);
                    mma_bf16(accB[mf][nf], al[mf], bh[nf]);
                }
        }
    }

    // epilogue
    #pragma unroll
    for (int mf = 0; mf < 2; mf++) {
        #pragma unroll
        for (int nf = 0; nf < 2; nf++) {
            int ii = wn + nf * 8 + 2 * q;
            #pragma unroll
            for (int rs = 0; rs < 2; rs++) {
                int tr = wm + mf * 16 + g + rs * 8;
                size_t gb = bB + (size_t)(t0 + tr)*Dd + i0 + ii;
                float2 Ga = *(const float2*)&g_li[gb];
                float2 Gg = *(const float2*)&g_lf[gb];
                float2 sg = *(const float2*)&g_o[gb];
                float rd = g_den[(size_t)b*Tt + t0 + tr];
                float vA0 = accA[mf][nf][rs*2], vA1 = accA[mf][nf][rs*2+1];
                float vB0 = accB[mf][nf][rs*2], vB1 = accB[mf][nf][rs*2+1];
                float2 o;
                o.x = sg.x * (Ga.x*vB0 + Gg.x*vA0) * rd;
                o.y = sg.y * (Ga.y*vB1 + Gg.y*vA1) * rd;
                *(float2*)&out[gb] = o;
            }
        }
    }
}

// ---------------------------------------------------------------------------
// RMSNorm in place
// ---------------------------------------------------------------------------
__global__ __launch_bounds__(256) void rmsnorm_kernel(float* __restrict__ out,
                                                      const float* __restrict__ ns)
{
    const int gw   = blockIdx.x * 8 + (threadIdx.x >> 5);
    const int lane = threadIdx.x & 31;
    size_t base = (size_t)gw * Dd + lane * 8;
    float4 a = *(const float4*)&out[base];
    float4 c = *(const float4*)&out[base + 4];
    float ss = a.x*a.x + a.y*a.y + a.z*a.z + a.w*a.w
             + c.x*c.x + c.y*c.y + c.z*c.z + c.w*c.w;
    #pragma unroll
    for (int o = 16; o; o >>= 1) ss += __shfl_xor_sync(0xffffffffu, ss, o);
    float rinv = rsqrtf(ss * (1.0f / Dd) + 1e-8f);
    float4 s1 = *(const float4*)&ns[lane * 8];
    float4 s2 = *(const float4*)&ns[lane * 8 + 4];
    a.x *= rinv * s1.x; a.y *= rinv * s1.y; a.z *= rinv * s1.z; a.w *= rinv * s1.w;
    c.x *= rinv * s2.x; c.y *= rinv * s2.y; c.z *= rinv * s2.z; c.w *= rinv * s2.w;
    *(float4*)&out[base]     = a;
    *(float4*)&out[base + 4] = c;
}

// ---------------------------------------------------------------------------
extern "C" void kernel_launch(void* const* d_in, const int* in_sizes, int n_in,
                              void* d_out, int out_size)
{
    const float* x  = (const float*)d_in[0];
    const float* Wq = (const float*)d_in[1];
    const float* bq = (const float*)d_in[2];
    const float* Wk = (const float*)d_in[3];
    const float* bk = (const float*)d_in[4];
    const float* Wv = (const float*)d_in[5];
    const float* bv = (const float*)d_in[6];
    const float* Wg = (const float*)d_in[7];
    const float* bg = (const float*)d_in[8];
    const float* ib = (const float*)d_in[9];
    const float* ns = (const float*)d_in[10];
    float* out = (float*)d_out;

    cudaFuncSetAttribute(state_scan, cudaFuncAttributeMaxDynamicSharedMemorySize,
                         SS_TOTAL * 4);

    dim3 ggrid(24, 64);
    proj_gemm<<<ggrid, 256>>>(x, Wq, bq, Wk, bk, Wv, bv, Wg, bg, ib);
    chanA<<<128, 256>>>();
    chanB<<<4, 256>>>();
    chanC<<<128, 256>>>();
    score_kernel<<<128, 256>>>();
    denom_kernel<<<1024, 256>>>();
    state_scan<<<128, 256, SS_TOTAL * 4>>>();
    combine<<<512, 256>>>(out);
    rmsnorm_kernel<<<1024, 256>>>(out, ns);
}